// round 2
// baseline (speedup 1.0000x reference)
#include <cuda_runtime.h>
#include <math.h>

#define BATCH 2
#define SEQ   2048
#define DIM   512
#define NH    8
#define DH    64
#define ROWS  (BATCH*SEQ)   // 4096

// Scratch (allocation-free rule: __device__ globals)
__device__ float g_xn [ROWS*DIM];   // layernormed x (Q path)
__device__ float g_q  [ROWS*DIM];
__device__ float g_k  [ROWS*DIM];
__device__ float g_v  [ROWS*DIM];
__device__ float g_ctx[ROWS*DIM];

// ---------------------------------------------------------------------------
// LayerNorm: one block per row, 128 threads x 4 elems
// ---------------------------------------------------------------------------
__global__ void __launch_bounds__(128) ln_kernel(const float* __restrict__ x,
                                                 const float* __restrict__ gamma,
                                                 const float* __restrict__ beta) {
    int row = blockIdx.x;
    int tid = threadIdx.x;
    const float* xr = x + row * DIM;

    float v[4];
    float sum = 0.f;
#pragma unroll
    for (int i = 0; i < 4; i++) { v[i] = xr[tid + i * 128]; sum += v[i]; }

    __shared__ float red[4];
    __shared__ float red2[4];
#pragma unroll
    for (int off = 16; off > 0; off >>= 1) sum += __shfl_xor_sync(0xffffffffu, sum, off);
    if ((tid & 31) == 0) red[tid >> 5] = sum;
    __syncthreads();
    float mean = (red[0] + red[1] + red[2] + red[3]) * (1.0f / DIM);

    float sq = 0.f;
#pragma unroll
    for (int i = 0; i < 4; i++) { float c = v[i] - mean; sq += c * c; }
#pragma unroll
    for (int off = 16; off > 0; off >>= 1) sq += __shfl_xor_sync(0xffffffffu, sq, off);
    if ((tid & 31) == 0) red2[tid >> 5] = sq;
    __syncthreads();
    float var = (red2[0] + red2[1] + red2[2] + red2[3]) * (1.0f / DIM);
    float rstd = rsqrtf(var + 1e-9f);

    float* outp = g_xn + row * DIM;
#pragma unroll
    for (int i = 0; i < 4; i++) {
        int c = tid + i * 128;
        outp[c] = gamma[c] * ((v[i] - mean) * rstd) + beta[c];
    }
}

// ---------------------------------------------------------------------------
// Tiled fp32 GEMM body: C[64x64 tile] = A[4096x512] * W[512x512] (+ R)
// block = (16,16), per-thread 4x4 microtile, K-chunks of 16
// ---------------------------------------------------------------------------
__device__ __forceinline__ void gemm_body(const float* __restrict__ A,
                                          const float* __restrict__ Wm,
                                          float* __restrict__ C,
                                          const float* __restrict__ R) {
    __shared__ float As[64][17];
    __shared__ float Bs[16][68];

    int tx = threadIdx.x, ty = threadIdx.y;
    int tid = ty * 16 + tx;
    int row0 = blockIdx.y * 64;
    int col0 = blockIdx.x * 64;

    int a_row = tid >> 2;         // 0..63
    int a_col = (tid & 3) * 4;    // 0,4,8,12
    int b_row = tid >> 4;         // 0..15
    int b_col = (tid & 15) * 4;   // 0..60

    float acc[4][4];
#pragma unroll
    for (int i = 0; i < 4; i++)
#pragma unroll
        for (int j = 0; j < 4; j++) acc[i][j] = 0.f;

    for (int k0 = 0; k0 < DIM; k0 += 16) {
        float4 av = *(const float4*)(A  + (row0 + a_row) * DIM + k0 + a_col);
        float4 bv = *(const float4*)(Wm + (k0 + b_row) * DIM + col0 + b_col);
        As[a_row][a_col + 0] = av.x; As[a_row][a_col + 1] = av.y;
        As[a_row][a_col + 2] = av.z; As[a_row][a_col + 3] = av.w;
        Bs[b_row][b_col + 0] = bv.x; Bs[b_row][b_col + 1] = bv.y;
        Bs[b_row][b_col + 2] = bv.z; Bs[b_row][b_col + 3] = bv.w;
        __syncthreads();
#pragma unroll
        for (int kk = 0; kk < 16; kk++) {
            float a[4], b[4];
#pragma unroll
            for (int i = 0; i < 4; i++) a[i] = As[ty * 4 + i][kk];
#pragma unroll
            for (int j = 0; j < 4; j++) b[j] = Bs[kk][tx * 4 + j];
#pragma unroll
            for (int i = 0; i < 4; i++)
#pragma unroll
                for (int j = 0; j < 4; j++) acc[i][j] += a[i] * b[j];
        }
        __syncthreads();
    }

#pragma unroll
    for (int i = 0; i < 4; i++) {
        int r = row0 + ty * 4 + i;
#pragma unroll
        for (int j = 0; j < 4; j++) {
            int c = col0 + tx * 4 + j;
            float val = acc[i][j];
            if (R) val += R[r * DIM + c];
            C[r * DIM + c] = val;
        }
    }
}

__global__ void __launch_bounds__(256) gemm_qkv_kernel(const float* __restrict__ x,
                                                       const float* __restrict__ Wq,
                                                       const float* __restrict__ Wk,
                                                       const float* __restrict__ Wv) {
    const float* A; const float* Wm; float* C;
    if (blockIdx.z == 0)      { A = g_xn; Wm = Wq; C = g_q; }
    else if (blockIdx.z == 1) { A = x;    Wm = Wk; C = g_k; }
    else                      { A = x;    Wm = Wv; C = g_v; }
    gemm_body(A, Wm, C, nullptr);
}

__global__ void __launch_bounds__(256) gemm_out_kernel(const float* __restrict__ Wo,
                                                       const float* __restrict__ x,
                                                       float* __restrict__ out) {
    gemm_body(g_ctx, Wo, out, x);
}

// ---------------------------------------------------------------------------
// Flash attention: grid (SEQ/64, NH, BATCH), 64 threads, 1 query-row/thread.
// Streams 64-key K/V tiles through smem, online softmax, O in registers.
// ---------------------------------------------------------------------------
__global__ void __launch_bounds__(64) flash_kernel() {
    int qb = blockIdx.x;
    int h  = blockIdx.y;
    int b  = blockIdx.z;
    int r  = threadIdx.x;          // query row within tile

    __shared__ float Ks[64][64];
    __shared__ float Vs[64][64];
    __shared__ float Ss[64][64];   // [key][queryrow] -> all lane accesses conflict-free

    int qrow = b * SEQ + qb * 64 + r;
    const float* Qp = g_q + qrow * DIM + h * DH;

    float q[DH], o[DH];
#pragma unroll
    for (int d = 0; d < DH; d += 4) {
        float4 t = *(const float4*)(Qp + d);
        q[d] = t.x; q[d + 1] = t.y; q[d + 2] = t.z; q[d + 3] = t.w;
    }
#pragma unroll
    for (int d = 0; d < DH; d++) o[d] = 0.f;

    float m = -1e30f, l = 0.f;

    int lrow = r >> 4;             // 0..3
    int lcol = (r & 15) * 4;       // 0..60

    for (int kt = 0; kt < SEQ / 64; kt++) {
        int kbase = b * SEQ + kt * 64;
#pragma unroll
        for (int it = 0; it < 16; it++) {
            int row = it * 4 + lrow;
            const float* Kp = g_k + (kbase + row) * DIM + h * DH + lcol;
            const float* Vp = g_v + (kbase + row) * DIM + h * DH + lcol;
            *(float4*)(&Ks[row][lcol]) = *(const float4*)Kp;
            *(float4*)(&Vs[row][lcol]) = *(const float4*)Vp;
        }
        __syncthreads();

        // scores for my row vs 64 keys
        float tmax = -1e30f;
        for (int c = 0; c < 64; c++) {
            float s0 = 0.f, s1 = 0.f, s2 = 0.f, s3 = 0.f;
#pragma unroll
            for (int d = 0; d < DH; d += 4) {
                s0 += q[d + 0] * Ks[c][d + 0];
                s1 += q[d + 1] * Ks[c][d + 1];
                s2 += q[d + 2] * Ks[c][d + 2];
                s3 += q[d + 3] * Ks[c][d + 3];
            }
            float s = ((s0 + s1) + (s2 + s3)) * 0.125f;  // 1/sqrt(64)
            Ss[c][r] = s;
            tmax = fmaxf(tmax, s);
        }

        float newm = fmaxf(m, tmax);
        float corr = __expf(m - newm);
#pragma unroll
        for (int d = 0; d < DH; d++) o[d] *= corr;

        float psum = 0.f;
        for (int c = 0; c < 64; c++) {
            float p = __expf(Ss[c][r] - newm);
            psum += p;
#pragma unroll
            for (int d = 0; d < DH; d++) o[d] += p * Vs[c][d];
        }
        l = l * corr + psum;
        m = newm;
        __syncthreads();
    }

    float inv = 1.f / l;
    float* outp = g_ctx + qrow * DIM + h * DH;
#pragma unroll
    for (int d = 0; d < DH; d += 4) {
        float4 t = make_float4(o[d] * inv, o[d + 1] * inv, o[d + 2] * inv, o[d + 3] * inv);
        *(float4*)(outp + d) = t;
    }
}

// ---------------------------------------------------------------------------
extern "C" void kernel_launch(void* const* d_in, const int* in_sizes, int n_in,
                              void* d_out, int out_size) {
    const float* x     = (const float*)d_in[0];
    const float* Wq    = (const float*)d_in[1];
    const float* Wk    = (const float*)d_in[2];
    const float* Wv    = (const float*)d_in[3];
    const float* Wo    = (const float*)d_in[4];
    const float* gamma = (const float*)d_in[5];
    const float* beta  = (const float*)d_in[6];
    float* out = (float*)d_out;

    ln_kernel<<<ROWS, 128>>>(x, gamma, beta);
    gemm_qkv_kernel<<<dim3(8, 64, 3), dim3(16, 16)>>>(x, Wq, Wk, Wv);
    flash_kernel<<<dim3(SEQ / 64, NH, BATCH), 64>>>();
    gemm_out_kernel<<<dim3(8, 64), dim3(16, 16)>>>(Wo, x, out);
}

// round 6
// speedup vs baseline: 2.3948x; 2.3948x over previous
#include <cuda_runtime.h>
#include <math.h>

#define BATCH 2
#define SEQ   2048
#define DIM   512
#define NH    8
#define DH    64
#define ROWS  (BATCH*SEQ)   // 4096

// Scratch (allocation-free rule: __device__ globals)
__device__ float g_xn [ROWS*DIM];   // layernormed x (Q path)
__device__ float g_q  [ROWS*DIM];   // tf32-rounded, pre-scaled by 0.125
__device__ float g_k  [ROWS*DIM];   // tf32-rounded
__device__ float g_v  [ROWS*DIM];   // tf32-rounded
__device__ float g_ctx[ROWS*DIM];

// ---------------------------------------------------------------------------
// helpers
// ---------------------------------------------------------------------------
__device__ __forceinline__ unsigned f2tf32(float x) {
    unsigned r;
    asm("cvt.rna.tf32.f32 %0, %1;" : "=r"(r) : "f"(x));
    return r;
}
__device__ __forceinline__ float tf32r(float x) {
    return __uint_as_float(f2tf32(x));
}
__device__ __forceinline__ void mma_tf32(float c[4], const unsigned a[4],
                                         unsigned b0, unsigned b1) {
    asm volatile(
        "mma.sync.aligned.m16n8k8.row.col.f32.tf32.tf32.f32 "
        "{%0,%1,%2,%3},{%4,%5,%6,%7},{%8,%9},{%0,%1,%2,%3};\n"
        : "+f"(c[0]), "+f"(c[1]), "+f"(c[2]), "+f"(c[3])
        : "r"(a[0]), "r"(a[1]), "r"(a[2]), "r"(a[3]), "r"(b0), "r"(b1));
}

// ---------------------------------------------------------------------------
// LayerNorm: one block per row, 128 threads x 4 elems
// ---------------------------------------------------------------------------
__global__ void __launch_bounds__(128) ln_kernel(const float* __restrict__ x,
                                                 const float* __restrict__ gamma,
                                                 const float* __restrict__ beta) {
    int row = blockIdx.x;
    int tid = threadIdx.x;
    const float* xr = x + row * DIM;

    float v[4];
    float sum = 0.f;
#pragma unroll
    for (int i = 0; i < 4; i++) { v[i] = xr[tid + i * 128]; sum += v[i]; }

    __shared__ float red[4];
    __shared__ float red2[4];
#pragma unroll
    for (int off = 16; off > 0; off >>= 1) sum += __shfl_xor_sync(0xffffffffu, sum, off);
    if ((tid & 31) == 0) red[tid >> 5] = sum;
    __syncthreads();
    float mean = (red[0] + red[1] + red[2] + red[3]) * (1.0f / DIM);

    float sq = 0.f;
#pragma unroll
    for (int i = 0; i < 4; i++) { float c = v[i] - mean; sq += c * c; }
#pragma unroll
    for (int off = 16; off > 0; off >>= 1) sq += __shfl_xor_sync(0xffffffffu, sq, off);
    if ((tid & 31) == 0) red2[tid >> 5] = sq;
    __syncthreads();
    float var = (red2[0] + red2[1] + red2[2] + red2[3]) * (1.0f / DIM);
    float rstd = rsqrtf(var + 1e-9f);

    float* outp = g_xn + row * DIM;
#pragma unroll
    for (int i = 0; i < 4; i++) {
        int c = tid + i * 128;
        outp[c] = gamma[c] * ((v[i] - mean) * rstd) + beta[c];
    }
}

// ---------------------------------------------------------------------------
// Tensor-core tf32 GEMM: C[4096x512] = A[4096x512] * W[512x512] (+R)
// block 128 thr (4 warps, 2x2), tile 64x64, BK=32
// ---------------------------------------------------------------------------
__device__ __forceinline__ void gemm_tc_body(const float* __restrict__ A,
                                             const float* __restrict__ Wm,
                                             float* __restrict__ C,
                                             const float* __restrict__ R,
                                             float oscale, bool cvt_out) {
    __shared__ float As[64][36];   // [m][k]  bank ≡ 4m+k → conflict-free frags
    __shared__ float Bs[32][72];   // [k][n]  bank ≡ 8k+n → conflict-free frags

    int tid = threadIdx.x;
    int w = tid >> 5, lane = tid & 31;
    int g = lane >> 2, tig = lane & 3;
    int wr = w >> 1, wc = w & 1;
    int row0 = blockIdx.y * 64;
    int col0 = blockIdx.x * 64;

    float acc[2][4][4];
#pragma unroll
    for (int i = 0; i < 2; i++)
#pragma unroll
        for (int j = 0; j < 4; j++)
#pragma unroll
            for (int e = 0; e < 4; e++) acc[i][j][e] = 0.f;

    for (int k0 = 0; k0 < DIM; k0 += 32) {
        // stage A tile 64x32 (tf32-round)
#pragma unroll
        for (int t = 0; t < 4; t++) {
            int idx = tid + t * 128;
            int r = idx >> 3, c4 = idx & 7;
            float4 v = *(const float4*)(A + (row0 + r) * DIM + k0 + c4 * 4);
            float4 o = make_float4(tf32r(v.x), tf32r(v.y), tf32r(v.z), tf32r(v.w));
            *(float4*)(&As[r][c4 * 4]) = o;
        }
        // stage B tile 32x64 (tf32-round)
#pragma unroll
        for (int t = 0; t < 4; t++) {
            int idx = tid + t * 128;
            int r = idx >> 4, c4 = idx & 15;
            float4 v = *(const float4*)(Wm + (k0 + r) * DIM + col0 + c4 * 4);
            float4 o = make_float4(tf32r(v.x), tf32r(v.y), tf32r(v.z), tf32r(v.w));
            *(float4*)(&Bs[r][c4 * 4]) = o;
        }
        __syncthreads();

#pragma unroll
        for (int ks = 0; ks < 4; ks++) {
            unsigned a[2][4];
#pragma unroll
            for (int i = 0; i < 2; i++) {
                int rb = wr * 32 + i * 16;
                a[i][0] = __float_as_uint(As[rb + g][ks * 8 + tig]);
                a[i][1] = __float_as_uint(As[rb + g + 8][ks * 8 + tig]);
                a[i][2] = __float_as_uint(As[rb + g][ks * 8 + tig + 4]);
                a[i][3] = __float_as_uint(As[rb + g + 8][ks * 8 + tig + 4]);
            }
#pragma unroll
            for (int j = 0; j < 4; j++) {
                unsigned b0 = __float_as_uint(Bs[ks * 8 + tig][wc * 32 + j * 8 + g]);
                unsigned b1 = __float_as_uint(Bs[ks * 8 + tig + 4][wc * 32 + j * 8 + g]);
                mma_tf32(acc[0][j], a[0], b0, b1);
                mma_tf32(acc[1][j], a[1], b0, b1);
            }
        }
        __syncthreads();
    }

    // epilogue: c0=(g,2t) c1=(g,2t+1) c2=(g+8,2t) c3=(g+8,2t+1)
#pragma unroll
    for (int i = 0; i < 2; i++) {
        int r = row0 + wr * 32 + i * 16 + g;
#pragma unroll
        for (int j = 0; j < 4; j++) {
            int c = col0 + wc * 32 + j * 8 + 2 * tig;
            float v0 = acc[i][j][0] * oscale;
            float v1 = acc[i][j][1] * oscale;
            float v2 = acc[i][j][2] * oscale;
            float v3 = acc[i][j][3] * oscale;
            if (R) {
                v0 += R[r * DIM + c];     v1 += R[r * DIM + c + 1];
                v2 += R[(r + 8) * DIM + c]; v3 += R[(r + 8) * DIM + c + 1];
            }
            if (cvt_out) {
                v0 = tf32r(v0); v1 = tf32r(v1); v2 = tf32r(v2); v3 = tf32r(v3);
            }
            *(float2*)(C + r * DIM + c)       = make_float2(v0, v1);
            *(float2*)(C + (r + 8) * DIM + c) = make_float2(v2, v3);
        }
    }
}

__global__ void __launch_bounds__(128) gemm_qkv_kernel(const float* __restrict__ x,
                                                       const float* __restrict__ Wq,
                                                       const float* __restrict__ Wk,
                                                       const float* __restrict__ Wv) {
    const float* A; const float* Wm; float* C; float sc;
    if (blockIdx.z == 0)      { A = g_xn; Wm = Wq; C = g_q; sc = 0.125f; } // fold 1/sqrt(dh)
    else if (blockIdx.z == 1) { A = x;    Wm = Wk; C = g_k; sc = 1.0f; }
    else                      { A = x;    Wm = Wv; C = g_v; sc = 1.0f; }
    gemm_tc_body(A, Wm, C, nullptr, sc, true);
}

__global__ void __launch_bounds__(128) gemm_out_kernel(const float* __restrict__ Wo,
                                                       const float* __restrict__ x,
                                                       float* __restrict__ out) {
    gemm_tc_body(g_ctx, Wo, out, x, 1.0f, false);
}

// ---------------------------------------------------------------------------
// Flash attention, tensor-core tf32.
// grid (32, 8, 2), block 128 = 4 warps; warp w owns 16 query rows.
// Q frags resident in registers; S->P relayout via shfl (no smem P).
// ---------------------------------------------------------------------------
__global__ void __launch_bounds__(128) flash_kernel() {
    int qb = blockIdx.x, h = blockIdx.y, b = blockIdx.z;
    int tid = threadIdx.x;
    int w = tid >> 5, lane = tid & 31;
    int g = lane >> 2, tig = lane & 3;

    __shared__ float Ks[64][68];   // bank ≡ 4row+col
    __shared__ float Vs[64][72];   // bank ≡ 8row+col

    int qrow0 = b * SEQ + qb * 64;

    // stage Q (already tf32-rounded & scaled) into Ks, build reg-resident A frags
#pragma unroll
    for (int t = 0; t < 8; t++) {
        int idx = tid + t * 128;
        int row = idx >> 4, c4 = idx & 15;
        *(float4*)(&Ks[row][c4 * 4]) =
            *(const float4*)(g_q + (qrow0 + row) * DIM + h * DH + c4 * 4);
    }
    __syncthreads();
    unsigned qf[8][4];
    int rb = w * 16;
#pragma unroll
    for (int ks = 0; ks < 8; ks++) {
        qf[ks][0] = __float_as_uint(Ks[rb + g][ks * 8 + tig]);
        qf[ks][1] = __float_as_uint(Ks[rb + g + 8][ks * 8 + tig]);
        qf[ks][2] = __float_as_uint(Ks[rb + g][ks * 8 + tig + 4]);
        qf[ks][3] = __float_as_uint(Ks[rb + g + 8][ks * 8 + tig + 4]);
    }
    __syncthreads();

    float o[8][4];
#pragma unroll
    for (int j = 0; j < 8; j++)
#pragma unroll
        for (int e = 0; e < 4; e++) o[j][e] = 0.f;
    float m0 = -1e30f, m1 = -1e30f, l0 = 0.f, l1 = 0.f;

    int srcA = (lane & 28) | (tig >> 1);
    int srcB = srcA + 2;
    bool oddc = tig & 1;

    for (int kt = 0; kt < SEQ / 64; kt++) {
        int kb = b * SEQ + kt * 64;
#pragma unroll
        for (int t = 0; t < 8; t++) {
            int idx = tid + t * 128;
            int row = idx >> 4, c4 = idx & 15;
            const float* Kp = g_k + (kb + row) * DIM + h * DH + c4 * 4;
            const float* Vp = g_v + (kb + row) * DIM + h * DH + c4 * 4;
            *(float4*)(&Ks[row][c4 * 4]) = *(const float4*)Kp;
            *(float4*)(&Vs[row][c4 * 4]) = *(const float4*)Vp;
        }
        __syncthreads();

        // S = Q K^T (scale pre-folded into Q)
        float s[8][4];
#pragma unroll
        for (int j = 0; j < 8; j++) {
            s[j][0] = 0.f; s[j][1] = 0.f; s[j][2] = 0.f; s[j][3] = 0.f;
#pragma unroll
            for (int ks = 0; ks < 8; ks++) {
                unsigned b0 = __float_as_uint(Ks[j * 8 + g][ks * 8 + tig]);
                unsigned b1 = __float_as_uint(Ks[j * 8 + g][ks * 8 + tig + 4]);
                mma_tf32(s[j], qf[ks], b0, b1);
            }
        }

        // online softmax: rows g (s0,s1) and g+8 (s2,s3)
        float tm0 = -1e30f, tm1 = -1e30f;
#pragma unroll
        for (int j = 0; j < 8; j++) {
            tm0 = fmaxf(tm0, fmaxf(s[j][0], s[j][1]));
            tm1 = fmaxf(tm1, fmaxf(s[j][2], s[j][3]));
        }
        tm0 = fmaxf(tm0, __shfl_xor_sync(0xffffffffu, tm0, 1));
        tm0 = fmaxf(tm0, __shfl_xor_sync(0xffffffffu, tm0, 2));
        tm1 = fmaxf(tm1, __shfl_xor_sync(0xffffffffu, tm1, 1));
        tm1 = fmaxf(tm1, __shfl_xor_sync(0xffffffffu, tm1, 2));

        float nm0 = fmaxf(m0, tm0), nm1 = fmaxf(m1, tm1);
        float cr0 = __expf(m0 - nm0), cr1 = __expf(m1 - nm1);
        l0 *= cr0; l1 *= cr1;
#pragma unroll
        for (int j = 0; j < 8; j++) {
            o[j][0] *= cr0; o[j][1] *= cr0; o[j][2] *= cr1; o[j][3] *= cr1;
        }

        float ls0 = 0.f, ls1 = 0.f;
#pragma unroll
        for (int j = 0; j < 8; j++) {
            float p0 = tf32r(__expf(s[j][0] - nm0));
            float p1 = tf32r(__expf(s[j][1] - nm0));
            float p2 = tf32r(__expf(s[j][2] - nm1));
            float p3 = tf32r(__expf(s[j][3] - nm1));
            ls0 += p0 + p1; ls1 += p2 + p3;
            s[j][0] = p0; s[j][1] = p1; s[j][2] = p2; s[j][3] = p3;
        }
        ls0 += __shfl_xor_sync(0xffffffffu, ls0, 1);
        ls0 += __shfl_xor_sync(0xffffffffu, ls0, 2);
        ls1 += __shfl_xor_sync(0xffffffffu, ls1, 1);
        ls1 += __shfl_xor_sync(0xffffffffu, ls1, 2);
        l0 += ls0; l1 += ls1; m0 = nm0; m1 = nm1;

        // O += P V : relayout P C-frag -> A-frag via shfl, then mma
#pragma unroll
        for (int ks = 0; ks < 8; ks++) {
            float v00 = __shfl_sync(0xffffffffu, s[ks][0], srcA);
            float v10 = __shfl_sync(0xffffffffu, s[ks][1], srcA);
            float v20 = __shfl_sync(0xffffffffu, s[ks][2], srcA);
            float v30 = __shfl_sync(0xffffffffu, s[ks][3], srcA);
            float v01 = __shfl_sync(0xffffffffu, s[ks][0], srcB);
            float v11 = __shfl_sync(0xffffffffu, s[ks][1], srcB);
            float v21 = __shfl_sync(0xffffffffu, s[ks][2], srcB);
            float v31 = __shfl_sync(0xffffffffu, s[ks][3], srcB);
            unsigned a[4];
            a[0] = __float_as_uint(oddc ? v10 : v00);
            a[1] = __float_as_uint(oddc ? v30 : v20);
            a[2] = __float_as_uint(oddc ? v11 : v01);
            a[3] = __float_as_uint(oddc ? v31 : v21);
#pragma unroll
            for (int j = 0; j < 8; j++) {
                unsigned b0 = __float_as_uint(Vs[ks * 8 + tig][j * 8 + g]);
                unsigned b1 = __float_as_uint(Vs[ks * 8 + tig + 4][j * 8 + g]);
                mma_tf32(o[j], a, b0, b1);
            }
        }
        __syncthreads();
    }

    float i0 = 1.f / l0, i1 = 1.f / l1;
    int r0 = qrow0 + rb + g;
#pragma unroll
    for (int j = 0; j < 8; j++) {
        int c = h * DH + j * 8 + 2 * tig;
        *(float2*)(g_ctx + r0 * DIM + c)       = make_float2(o[j][0] * i0, o[j][1] * i0);
        *(float2*)(g_ctx + (r0 + 8) * DIM + c) = make_float2(o[j][2] * i1, o[j][3] * i1);
    }
}

// ---------------------------------------------------------------------------
extern "C" void kernel_launch(void* const* d_in, const int* in_sizes, int n_in,
                              void* d_out, int out_size) {
    const float* x     = (const float*)d_in[0];
    const float* Wq    = (const float*)d_in[1];
    const float* Wk    = (const float*)d_in[2];
    const float* Wv    = (const float*)d_in[3];
    const float* Wo    = (const float*)d_in[4];
    const float* gamma = (const float*)d_in[5];
    const float* beta  = (const float*)d_in[6];
    float* out = (float*)d_out;

    ln_kernel<<<ROWS, 128>>>(x, gamma, beta);
    gemm_qkv_kernel<<<dim3(8, 64, 3), 128>>>(x, Wq, Wk, Wv);
    flash_kernel<<<dim3(SEQ / 64, NH, BATCH), 128>>>();
    gemm_out_kernel<<<dim3(8, 64), 128>>>(Wo, x, out);
}

// round 9
// speedup vs baseline: 4.0052x; 1.6725x over previous
#include <cuda_runtime.h>
#include <math.h>

#define BATCH 2
#define SEQ   2048
#define DIM   512
#define NH    8
#define DH    64
#define ROWS  (BATCH*SEQ)   // 4096

// Scratch (allocation-free rule: __device__ globals)
__device__ float g_xn [ROWS*DIM];   // layernormed x (Q path)
__device__ float g_q  [ROWS*DIM];   // pre-scaled by 0.125 (1/sqrt(dh))
__device__ float g_k  [ROWS*DIM];
__device__ float g_v  [ROWS*DIM];
__device__ float g_ctx[ROWS*DIM];

// ---------------------------------------------------------------------------
// helpers
// ---------------------------------------------------------------------------
__device__ __forceinline__ void mma_tf32(float c[4], const unsigned a[4],
                                         unsigned b0, unsigned b1) {
    asm volatile(
        "mma.sync.aligned.m16n8k8.row.col.f32.tf32.tf32.f32 "
        "{%0,%1,%2,%3},{%4,%5,%6,%7},{%8,%9},{%0,%1,%2,%3};\n"
        : "+f"(c[0]), "+f"(c[1]), "+f"(c[2]), "+f"(c[3])
        : "r"(a[0]), "r"(a[1]), "r"(a[2]), "r"(a[3]), "r"(b0), "r"(b1));
}
__device__ __forceinline__ void cpa16(unsigned dst, const void* src) {
    asm volatile("cp.async.cg.shared.global [%0], [%1], 16;\n" :: "r"(dst), "l"(src));
}
__device__ __forceinline__ void cp_commit() {
    asm volatile("cp.async.commit_group;\n");
}
template<int N>
__device__ __forceinline__ void cp_wait() {
    asm volatile("cp.async.wait_group %0;\n" :: "n"(N));
}

// ---------------------------------------------------------------------------
// LayerNorm: one block per row, 128 threads x 4 elems
// ---------------------------------------------------------------------------
__global__ void __launch_bounds__(128) ln_kernel(const float* __restrict__ x,
                                                 const float* __restrict__ gamma,
                                                 const float* __restrict__ beta) {
    int row = blockIdx.x;
    int tid = threadIdx.x;
    const float* xr = x + row * DIM;

    float v[4];
    float sum = 0.f;
#pragma unroll
    for (int i = 0; i < 4; i++) { v[i] = xr[tid + i * 128]; sum += v[i]; }

    __shared__ float red[4];
    __shared__ float red2[4];
#pragma unroll
    for (int off = 16; off > 0; off >>= 1) sum += __shfl_xor_sync(0xffffffffu, sum, off);
    if ((tid & 31) == 0) red[tid >> 5] = sum;
    __syncthreads();
    float mean = (red[0] + red[1] + red[2] + red[3]) * (1.0f / DIM);

    float sq = 0.f;
#pragma unroll
    for (int i = 0; i < 4; i++) { float c = v[i] - mean; sq += c * c; }
#pragma unroll
    for (int off = 16; off > 0; off >>= 1) sq += __shfl_xor_sync(0xffffffffu, sq, off);
    if ((tid & 31) == 0) red2[tid >> 5] = sq;
    __syncthreads();
    float var = (red2[0] + red2[1] + red2[2] + red2[3]) * (1.0f / DIM);
    float rstd = rsqrtf(var + 1e-9f);

    float* outp = g_xn + row * DIM;
#pragma unroll
    for (int i = 0; i < 4; i++) {
        int c = tid + i * 128;
        outp[c] = gamma[c] * ((v[i] - mean) * rstd) + beta[c];
    }
}

// ---------------------------------------------------------------------------
// Tensor-core tf32 GEMM with cp.async double-buffer.
// C[4096x512] = A[4096x512] * W[512x512] (+R)
// block 256 thr (8 warps: 4x2), CTA tile 128x64, BK=16.
// ---------------------------------------------------------------------------
#define BM 128
#define BN 64
#define BK 16

__device__ __forceinline__ void gemm_tc_body(const float* __restrict__ A,
                                             const float* __restrict__ Wm,
                                             float* __restrict__ C,
                                             const float* __restrict__ R,
                                             float oscale) {
    __shared__ float As[2][BM][20];   // [m][k] bank ≡ (20m+k)%32 → frag-conflict-free
    __shared__ float Bs[2][BK][72];   // [k][n] bank ≡ (8k+n)%32  → frag-conflict-free

    int tid = threadIdx.x;
    int w = tid >> 5, lane = tid & 31;
    int g = lane >> 2, tig = lane & 3;
    int wr = w >> 1, wc = w & 1;         // 4x2 warp grid, warp tile 32x32
    int row0 = blockIdx.y * BM;
    int col0 = blockIdx.x * BN;

    unsigned sA = (unsigned)__cvta_generic_to_shared(&As[0][0][0]);
    unsigned sB = (unsigned)__cvta_generic_to_shared(&Bs[0][0][0]);

    // A-copy indices: 512 float4 chunks, 2 per thread
    int ar0 = tid >> 2, ac0 = (tid & 3) * 4;
    int ar1 = (tid + 256) >> 2, ac1 = ((tid + 256) & 3) * 4;
    // B-copy: 256 chunks, 1 per thread
    int br = tid >> 4, bc = (tid & 15) * 4;

    float acc[2][4][4];
#pragma unroll
    for (int i = 0; i < 2; i++)
#pragma unroll
        for (int j = 0; j < 4; j++)
#pragma unroll
            for (int e = 0; e < 4; e++) acc[i][j][e] = 0.f;

    auto stage = [&](int buf, int k0) {
        cpa16(sA + (unsigned)(buf * (BM * 20 * 4) + (ar0 * 20 + ac0) * 4),
              A + (row0 + ar0) * DIM + k0 + ac0);
        cpa16(sA + (unsigned)(buf * (BM * 20 * 4) + (ar1 * 20 + ac1) * 4),
              A + (row0 + ar1) * DIM + k0 + ac1);
        cpa16(sB + (unsigned)(buf * (BK * 72 * 4) + (br * 72 + bc) * 4),
              Wm + (k0 + br) * DIM + col0 + bc);
    };

    stage(0, 0);
    cp_commit();

    const int NIT = DIM / BK;   // 32
    for (int it = 0; it < NIT; it++) {
        int buf = it & 1;
        if (it + 1 < NIT) {
            stage(buf ^ 1, (it + 1) * BK);
            cp_commit();
            cp_wait<1>();
        } else {
            cp_wait<0>();
        }
        __syncthreads();

#pragma unroll
        for (int ks = 0; ks < 2; ks++) {
            unsigned a[2][4];
#pragma unroll
            for (int i = 0; i < 2; i++) {
                int rb = wr * 32 + i * 16;
                a[i][0] = __float_as_uint(As[buf][rb + g][ks * 8 + tig]);
                a[i][1] = __float_as_uint(As[buf][rb + g + 8][ks * 8 + tig]);
                a[i][2] = __float_as_uint(As[buf][rb + g][ks * 8 + tig + 4]);
                a[i][3] = __float_as_uint(As[buf][rb + g + 8][ks * 8 + tig + 4]);
            }
#pragma unroll
            for (int j = 0; j < 4; j++) {
                unsigned b0 = __float_as_uint(Bs[buf][ks * 8 + tig][wc * 32 + j * 8 + g]);
                unsigned b1 = __float_as_uint(Bs[buf][ks * 8 + tig + 4][wc * 32 + j * 8 + g]);
                mma_tf32(acc[0][j], a[0], b0, b1);
                mma_tf32(acc[1][j], a[1], b0, b1);
            }
        }
        __syncthreads();
    }

    // epilogue: c0=(g,2t) c1=(g,2t+1) c2=(g+8,2t) c3=(g+8,2t+1)
#pragma unroll
    for (int i = 0; i < 2; i++) {
        int r = row0 + wr * 32 + i * 16 + g;
#pragma unroll
        for (int j = 0; j < 4; j++) {
            int c = col0 + wc * 32 + j * 8 + 2 * tig;
            float v0 = acc[i][j][0] * oscale;
            float v1 = acc[i][j][1] * oscale;
            float v2 = acc[i][j][2] * oscale;
            float v3 = acc[i][j][3] * oscale;
            if (R) {
                v0 += R[r * DIM + c];       v1 += R[r * DIM + c + 1];
                v2 += R[(r + 8) * DIM + c]; v3 += R[(r + 8) * DIM + c + 1];
            }
            *(float2*)(C + r * DIM + c)       = make_float2(v0, v1);
            *(float2*)(C + (r + 8) * DIM + c) = make_float2(v2, v3);
        }
    }
}

__global__ void __launch_bounds__(256) gemm_qkv_kernel(const float* __restrict__ x,
                                                       const float* __restrict__ Wq,
                                                       const float* __restrict__ Wk,
                                                       const float* __restrict__ Wv) {
    const float* A; const float* Wm; float* C; float sc;
    if (blockIdx.z == 0)      { A = g_xn; Wm = Wq; C = g_q; sc = 0.125f; } // fold 1/sqrt(dh)
    else if (blockIdx.z == 1) { A = x;    Wm = Wk; C = g_k; sc = 1.0f; }
    else                      { A = x;    Wm = Wv; C = g_v; sc = 1.0f; }
    gemm_tc_body(A, Wm, C, nullptr, sc);
}

__global__ void __launch_bounds__(256) gemm_out_kernel(const float* __restrict__ Wo,
                                                       const float* __restrict__ x,
                                                       float* __restrict__ out) {
    gemm_tc_body(g_ctx, Wo, out, x, 1.0f);
}

// ---------------------------------------------------------------------------
// Flash attention, tensor-core tf32, cp.async double-buffered 32-key tiles.
// grid (32, 8, 2), block 128 = 4 warps; warp w owns 16 query rows.
// Q frags loaded directly from gmem; S->P relayout via shfl (no smem P).
// ---------------------------------------------------------------------------
#define KT 32

__global__ void __launch_bounds__(128) flash_kernel() {
    int qb = blockIdx.x, h = blockIdx.y, b = blockIdx.z;
    int tid = threadIdx.x;
    int w = tid >> 5, lane = tid & 31;
    int g = lane >> 2, tig = lane & 3;

    __shared__ float Ks[2][KT][68];   // bank ≡ (4row+col)%32
    __shared__ float Vs[2][KT][72];   // bank ≡ (8row+col)%32

    unsigned sK = (unsigned)__cvta_generic_to_shared(&Ks[0][0][0]);
    unsigned sV = (unsigned)__cvta_generic_to_shared(&Vs[0][0][0]);

    int qrow0 = b * SEQ + qb * 64;
    int rb = w * 16;
    const float* Kb = g_k + (size_t)(b * SEQ) * DIM + h * DH;
    const float* Vb = g_v + (size_t)(b * SEQ) * DIM + h * DH;

    // copy indices: KT*16 = 512 chunks per array, 4 per thread
    auto stage = [&](int buf, int kt) {
#pragma unroll
        for (int t = 0; t < 4; t++) {
            int chunk = tid + t * 128;
            int row = chunk >> 4, c4 = (chunk & 15) * 4;
            const float* kp = Kb + (size_t)(kt * KT + row) * DIM + c4;
            const float* vp = Vb + (size_t)(kt * KT + row) * DIM + c4;
            cpa16(sK + (unsigned)(buf * (KT * 68 * 4) + (row * 68 + c4) * 4), kp);
            cpa16(sV + (unsigned)(buf * (KT * 72 * 4) + (row * 72 + c4) * 4), vp);
        }
    };

    stage(0, 0);
    cp_commit();

    // Q fragments straight from gmem (once)
    unsigned qf[8][4];
    const float* Qp = g_q + h * DH;
#pragma unroll
    for (int ks = 0; ks < 8; ks++) {
        int r0 = (qrow0 + rb + g) * DIM;
        int r1 = (qrow0 + rb + g + 8) * DIM;
        qf[ks][0] = __float_as_uint(Qp[r0 + ks * 8 + tig]);
        qf[ks][1] = __float_as_uint(Qp[r1 + ks * 8 + tig]);
        qf[ks][2] = __float_as_uint(Qp[r0 + ks * 8 + tig + 4]);
        qf[ks][3] = __float_as_uint(Qp[r1 + ks * 8 + tig + 4]);
    }

    float o[8][4];
#pragma unroll
    for (int j = 0; j < 8; j++)
#pragma unroll
        for (int e = 0; e < 4; e++) o[j][e] = 0.f;
    float m0 = -1e30f, m1 = -1e30f, l0 = 0.f, l1 = 0.f;

    int srcA = (lane & 28) | (tig >> 1);
    int srcB = srcA + 2;
    bool oddc = tig & 1;

    const int NT = SEQ / KT;   // 64
    for (int kt = 0; kt < NT; kt++) {
        int buf = kt & 1;
        if (kt + 1 < NT) {
            stage(buf ^ 1, kt + 1);
            cp_commit();
            cp_wait<1>();
        } else {
            cp_wait<0>();
        }
        __syncthreads();

        // S = Q K^T (scale pre-folded into Q): 32 keys -> 4 n8 blocks
        float s[4][4];
#pragma unroll
        for (int j = 0; j < 4; j++) {
            s[j][0] = 0.f; s[j][1] = 0.f; s[j][2] = 0.f; s[j][3] = 0.f;
#pragma unroll
            for (int ks = 0; ks < 8; ks++) {
                unsigned b0 = __float_as_uint(Ks[buf][j * 8 + g][ks * 8 + tig]);
                unsigned b1 = __float_as_uint(Ks[buf][j * 8 + g][ks * 8 + tig + 4]);
                mma_tf32(s[j], qf[ks], b0, b1);
            }
        }

        // online softmax: rows g (s0,s1) and g+8 (s2,s3)
        float tm0 = -1e30f, tm1 = -1e30f;
#pragma unroll
        for (int j = 0; j < 4; j++) {
            tm0 = fmaxf(tm0, fmaxf(s[j][0], s[j][1]));
            tm1 = fmaxf(tm1, fmaxf(s[j][2], s[j][3]));
        }
        tm0 = fmaxf(tm0, __shfl_xor_sync(0xffffffffu, tm0, 1));
        tm0 = fmaxf(tm0, __shfl_xor_sync(0xffffffffu, tm0, 2));
        tm1 = fmaxf(tm1, __shfl_xor_sync(0xffffffffu, tm1, 1));
        tm1 = fmaxf(tm1, __shfl_xor_sync(0xffffffffu, tm1, 2));

        float nm0 = fmaxf(m0, tm0), nm1 = fmaxf(m1, tm1);
        float cr0 = __expf(m0 - nm0), cr1 = __expf(m1 - nm1);
        l0 *= cr0; l1 *= cr1;
#pragma unroll
        for (int j = 0; j < 8; j++) {
            o[j][0] *= cr0; o[j][1] *= cr0; o[j][2] *= cr1; o[j][3] *= cr1;
        }

        float ls0 = 0.f, ls1 = 0.f;
#pragma unroll
        for (int j = 0; j < 4; j++) {
            float p0 = __expf(s[j][0] - nm0);
            float p1 = __expf(s[j][1] - nm0);
            float p2 = __expf(s[j][2] - nm1);
            float p3 = __expf(s[j][3] - nm1);
            ls0 += p0 + p1; ls1 += p2 + p3;
            s[j][0] = p0; s[j][1] = p1; s[j][2] = p2; s[j][3] = p3;
        }
        ls0 += __shfl_xor_sync(0xffffffffu, ls0, 1);
        ls0 += __shfl_xor_sync(0xffffffffu, ls0, 2);
        ls1 += __shfl_xor_sync(0xffffffffu, ls1, 1);
        ls1 += __shfl_xor_sync(0xffffffffu, ls1, 2);
        l0 += ls0; l1 += ls1; m0 = nm0; m1 = nm1;

        // O += P V : relayout P C-frag -> A-frag via shfl, then mma
#pragma unroll
        for (int ks2 = 0; ks2 < 4; ks2++) {
            float v00 = __shfl_sync(0xffffffffu, s[ks2][0], srcA);
            float v10 = __shfl_sync(0xffffffffu, s[ks2][1], srcA);
            float v20 = __shfl_sync(0xffffffffu, s[ks2][2], srcA);
            float v30 = __shfl_sync(0xffffffffu, s[ks2][3], srcA);
            float v01 = __shfl_sync(0xffffffffu, s[ks2][0], srcB);
            float v11 = __shfl_sync(0xffffffffu, s[ks2][1], srcB);
            float v21 = __shfl_sync(0xffffffffu, s[ks2][2], srcB);
            float v31 = __shfl_sync(0xffffffffu, s[ks2][3], srcB);
            unsigned a[4];
            a[0] = __float_as_uint(oddc ? v10 : v00);
            a[1] = __float_as_uint(oddc ? v30 : v20);
            a[2] = __float_as_uint(oddc ? v11 : v01);
            a[3] = __float_as_uint(oddc ? v31 : v21);
#pragma unroll
            for (int j = 0; j < 8; j++) {
                unsigned b0 = __float_as_uint(Vs[buf][ks2 * 8 + tig][j * 8 + g]);
                unsigned b1 = __float_as_uint(Vs[buf][ks2 * 8 + tig + 4][j * 8 + g]);
                mma_tf32(o[j], a, b0, b1);
            }
        }
        __syncthreads();
    }

    float i0 = 1.f / l0, i1 = 1.f / l1;
    int r0 = qrow0 + rb + g;
#pragma unroll
    for (int j = 0; j < 8; j++) {
        int c = h * DH + j * 8 + 2 * tig;
        *(float2*)(g_ctx + r0 * DIM + c)       = make_float2(o[j][0] * i0, o[j][1] * i0);
        *(float2*)(g_ctx + (r0 + 8) * DIM + c) = make_float2(o[j][2] * i1, o[j][3] * i1);
    }
}

// ---------------------------------------------------------------------------
extern "C" void kernel_launch(void* const* d_in, const int* in_sizes, int n_in,
                              void* d_out, int out_size) {
    const float* x     = (const float*)d_in[0];
    const float* Wq    = (const float*)d_in[1];
    const float* Wk    = (const float*)d_in[2];
    const float* Wv    = (const float*)d_in[3];
    const float* Wo    = (const float*)d_in[4];
    const float* gamma = (const float*)d_in[5];
    const float* beta  = (const float*)d_in[6];
    float* out = (float*)d_out;

    ln_kernel<<<ROWS, 128>>>(x, gamma, beta);
    gemm_qkv_kernel<<<dim3(DIM / BN, ROWS / BM, 3), 256>>>(x, Wq, Wk, Wv);
    flash_kernel<<<dim3(SEQ / 64, NH, BATCH), 128>>>();
    gemm_out_kernel<<<dim3(DIM / BN, ROWS / BM), 256>>>(Wo, x, out);
}

// round 11
// speedup vs baseline: 4.0771x; 1.0179x over previous
#include <cuda_runtime.h>
#include <math.h>

#define BATCH 2
#define SEQ   2048
#define DIM   512
#define NH    8
#define DH    64
#define ROWS  (BATCH*SEQ)   // 4096

// Scratch (allocation-free rule: __device__ globals)
__device__ float g_xn [ROWS*DIM];   // layernormed x (Q path)
__device__ float g_q  [ROWS*DIM];   // pre-scaled by 0.125 (1/sqrt(dh))
__device__ float g_k  [ROWS*DIM];
__device__ float g_v  [ROWS*DIM];
__device__ float g_ctx[ROWS*DIM];

// ---------------------------------------------------------------------------
// helpers
// ---------------------------------------------------------------------------
__device__ __forceinline__ void mma_tf32(float c[4], const unsigned a[4],
                                         unsigned b0, unsigned b1) {
    asm volatile(
        "mma.sync.aligned.m16n8k8.row.col.f32.tf32.tf32.f32 "
        "{%0,%1,%2,%3},{%4,%5,%6,%7},{%8,%9},{%0,%1,%2,%3};\n"
        : "+f"(c[0]), "+f"(c[1]), "+f"(c[2]), "+f"(c[3])
        : "r"(a[0]), "r"(a[1]), "r"(a[2]), "r"(a[3]), "r"(b0), "r"(b1));
}
__device__ __forceinline__ void cpa16(unsigned dst, const void* src) {
    asm volatile("cp.async.cg.shared.global [%0], [%1], 16;\n" :: "r"(dst), "l"(src));
}
__device__ __forceinline__ void cp_commit() {
    asm volatile("cp.async.commit_group;\n");
}
template<int N>
__device__ __forceinline__ void cp_wait() {
    asm volatile("cp.async.wait_group %0;\n" :: "n"(N));
}

// ---------------------------------------------------------------------------
// LayerNorm: one block per row, 128 threads, one float4 per thread
// ---------------------------------------------------------------------------
__global__ void __launch_bounds__(128) ln_kernel(const float* __restrict__ x,
                                                 const float* __restrict__ gamma,
                                                 const float* __restrict__ beta) {
    int row = blockIdx.x;
    int tid = threadIdx.x;

    float4 v = *(const float4*)(x + row * DIM + tid * 4);
    float sum = (v.x + v.y) + (v.z + v.w);

    __shared__ float red[4];
    __shared__ float red2[4];
#pragma unroll
    for (int off = 16; off > 0; off >>= 1) sum += __shfl_xor_sync(0xffffffffu, sum, off);
    if ((tid & 31) == 0) red[tid >> 5] = sum;
    __syncthreads();
    float mean = (red[0] + red[1] + red[2] + red[3]) * (1.0f / DIM);

    float cx = v.x - mean, cy = v.y - mean, cz = v.z - mean, cw = v.w - mean;
    float sq = (cx * cx + cy * cy) + (cz * cz + cw * cw);
#pragma unroll
    for (int off = 16; off > 0; off >>= 1) sq += __shfl_xor_sync(0xffffffffu, sq, off);
    if ((tid & 31) == 0) red2[tid >> 5] = sq;
    __syncthreads();
    float var = (red2[0] + red2[1] + red2[2] + red2[3]) * (1.0f / DIM);
    float rstd = rsqrtf(var + 1e-9f);

    float4 gm = *(const float4*)(gamma + tid * 4);
    float4 bt = *(const float4*)(beta + tid * 4);
    float4 o = make_float4(gm.x * (cx * rstd) + bt.x,
                           gm.y * (cy * rstd) + bt.y,
                           gm.z * (cz * rstd) + bt.z,
                           gm.w * (cw * rstd) + bt.w);
    *(float4*)(g_xn + row * DIM + tid * 4) = o;
}

// ---------------------------------------------------------------------------
// Tensor-core tf32 GEMM, 3-stage cp.async pipeline, ONE sync per K-chunk.
// C[4096x512] = A[4096x512] * W[512x512] (+R)
// block 256 thr (8 warps: 4x2), CTA tile 128x64, BK=16.
// ---------------------------------------------------------------------------
#define BM 128
#define BN 64
#define BK 16
#define NSTG 3

__device__ __forceinline__ void gemm_tc_body(const float* __restrict__ A,
                                             const float* __restrict__ Wm,
                                             float* __restrict__ C,
                                             const float* __restrict__ R,
                                             float oscale) {
    __shared__ float As[NSTG][BM][20];   // [m][k] bank ≡ (20m+k)%32 → frag-conflict-free
    __shared__ float Bs[NSTG][BK][72];   // [k][n] bank ≡ (8k+n)%32  → frag-conflict-free

    int tid = threadIdx.x;
    int w = tid >> 5, lane = tid & 31;
    int g = lane >> 2, tig = lane & 3;
    int wr = w >> 1, wc = w & 1;         // 4x2 warp grid, warp tile 32x32
    int row0 = blockIdx.y * BM;
    int col0 = blockIdx.x * BN;

    unsigned sA = (unsigned)__cvta_generic_to_shared(&As[0][0][0]);
    unsigned sB = (unsigned)__cvta_generic_to_shared(&Bs[0][0][0]);

    // A-copy indices: 512 float4 chunks, 2 per thread
    int ar0 = tid >> 2, ac0 = (tid & 3) * 4;
    int ar1 = (tid + 256) >> 2, ac1 = ((tid + 256) & 3) * 4;
    // B-copy: 256 chunks, 1 per thread
    int br = tid >> 4, bc = (tid & 15) * 4;

    float acc[2][4][4];
#pragma unroll
    for (int i = 0; i < 2; i++)
#pragma unroll
        for (int j = 0; j < 4; j++)
#pragma unroll
            for (int e = 0; e < 4; e++) acc[i][j][e] = 0.f;

    auto stage = [&](int buf, int k0) {
        cpa16(sA + (unsigned)(buf * (BM * 20 * 4) + (ar0 * 20 + ac0) * 4),
              A + (row0 + ar0) * DIM + k0 + ac0);
        cpa16(sA + (unsigned)(buf * (BM * 20 * 4) + (ar1 * 20 + ac1) * 4),
              A + (row0 + ar1) * DIM + k0 + ac1);
        cpa16(sB + (unsigned)(buf * (BK * 72 * 4) + (br * 72 + bc) * 4),
              Wm + (k0 + br) * DIM + col0 + bc);
    };

    stage(0, 0);        cp_commit();
    stage(1, BK);       cp_commit();

    const int NIT = DIM / BK;   // 32
    int buf = 0, nbuf = 2;      // nbuf = (it+2)%3 rolling
    for (int it = 0; it < NIT; it++) {
        if (it + 1 < NIT) cp_wait<1>(); else cp_wait<0>();
        __syncthreads();
        if (it + 2 < NIT) {
            stage(nbuf, (it + 2) * BK);
            cp_commit();
        }

#pragma unroll
        for (int ks = 0; ks < 2; ks++) {
            unsigned a[2][4];
#pragma unroll
            for (int i = 0; i < 2; i++) {
                int rb = wr * 32 + i * 16;
                a[i][0] = __float_as_uint(As[buf][rb + g][ks * 8 + tig]);
                a[i][1] = __float_as_uint(As[buf][rb + g + 8][ks * 8 + tig]);
                a[i][2] = __float_as_uint(As[buf][rb + g][ks * 8 + tig + 4]);
                a[i][3] = __float_as_uint(As[buf][rb + g + 8][ks * 8 + tig + 4]);
            }
#pragma unroll
            for (int j = 0; j < 4; j++) {
                unsigned b0 = __float_as_uint(Bs[buf][ks * 8 + tig][wc * 32 + j * 8 + g]);
                unsigned b1 = __float_as_uint(Bs[buf][ks * 8 + tig + 4][wc * 32 + j * 8 + g]);
                mma_tf32(acc[0][j], a[0], b0, b1);
                mma_tf32(acc[1][j], a[1], b0, b1);
            }
        }
        buf = (buf == 2) ? 0 : buf + 1;
        nbuf = (nbuf == 2) ? 0 : nbuf + 1;
    }

    // epilogue: c0=(g,2t) c1=(g,2t+1) c2=(g+8,2t) c3=(g+8,2t+1)
#pragma unroll
    for (int i = 0; i < 2; i++) {
        int r = row0 + wr * 32 + i * 16 + g;
#pragma unroll
        for (int j = 0; j < 4; j++) {
            int c = col0 + wc * 32 + j * 8 + 2 * tig;
            float v0 = acc[i][j][0] * oscale;
            float v1 = acc[i][j][1] * oscale;
            float v2 = acc[i][j][2] * oscale;
            float v3 = acc[i][j][3] * oscale;
            if (R) {
                v0 += R[r * DIM + c];       v1 += R[r * DIM + c + 1];
                v2 += R[(r + 8) * DIM + c]; v3 += R[(r + 8) * DIM + c + 1];
            }
            *(float2*)(C + r * DIM + c)       = make_float2(v0, v1);
            *(float2*)(C + (r + 8) * DIM + c) = make_float2(v2, v3);
        }
    }
}

__global__ void __launch_bounds__(256) gemm_qkv_kernel(const float* __restrict__ x,
                                                       const float* __restrict__ Wq,
                                                       const float* __restrict__ Wk,
                                                       const float* __restrict__ Wv) {
    const float* A; const float* Wm; float* C; float sc;
    if (blockIdx.z == 0)      { A = g_xn; Wm = Wq; C = g_q; sc = 0.125f; } // fold 1/sqrt(dh)
    else if (blockIdx.z == 1) { A = x;    Wm = Wk; C = g_k; sc = 1.0f; }
    else                      { A = x;    Wm = Wv; C = g_v; sc = 1.0f; }
    gemm_tc_body(A, Wm, C, nullptr, sc);
}

__global__ void __launch_bounds__(256) gemm_out_kernel(const float* __restrict__ Wo,
                                                       const float* __restrict__ x,
                                                       float* __restrict__ out) {
    gemm_tc_body(g_ctx, Wo, out, x, 1.0f);
}

// ---------------------------------------------------------------------------
// Flash attention, tensor-core tf32, cp.async double-buffer, ONE sync/tile.
// grid (32, 8, 2), block 128 = 4 warps; warp w owns 16 query rows.
// Q frags loaded directly from gmem; S->P relayout via shfl (no smem P).
// ---------------------------------------------------------------------------
#define KT 32

__global__ void __launch_bounds__(128) flash_kernel() {
    int qb = blockIdx.x, h = blockIdx.y, b = blockIdx.z;
    int tid = threadIdx.x;
    int w = tid >> 5, lane = tid & 31;
    int g = lane >> 2, tig = lane & 3;

    __shared__ float Ks[2][KT][68];   // bank ≡ (4row+col)%32
    __shared__ float Vs[2][KT][72];   // bank ≡ (8row+col)%32

    unsigned sK = (unsigned)__cvta_generic_to_shared(&Ks[0][0][0]);
    unsigned sV = (unsigned)__cvta_generic_to_shared(&Vs[0][0][0]);

    int qrow0 = b * SEQ + qb * 64;
    int rb = w * 16;
    const float* Kb = g_k + (size_t)(b * SEQ) * DIM + h * DH;
    const float* Vb = g_v + (size_t)(b * SEQ) * DIM + h * DH;

    // copy indices: KT*16 = 512 chunks per array, 4 per thread
    auto stage = [&](int buf, int kt) {
#pragma unroll
        for (int t = 0; t < 4; t++) {
            int chunk = tid + t * 128;
            int row = chunk >> 4, c4 = (chunk & 15) * 4;
            const float* kp = Kb + (size_t)(kt * KT + row) * DIM + c4;
            const float* vp = Vb + (size_t)(kt * KT + row) * DIM + c4;
            cpa16(sK + (unsigned)(buf * (KT * 68 * 4) + (row * 68 + c4) * 4), kp);
            cpa16(sV + (unsigned)(buf * (KT * 72 * 4) + (row * 72 + c4) * 4), vp);
        }
    };

    stage(0, 0);
    cp_commit();

    // Q fragments straight from gmem (once)
    unsigned qf[8][4];
    const float* Qp = g_q + h * DH;
#pragma unroll
    for (int ks = 0; ks < 8; ks++) {
        int r0 = (qrow0 + rb + g) * DIM;
        int r1 = (qrow0 + rb + g + 8) * DIM;
        qf[ks][0] = __float_as_uint(Qp[r0 + ks * 8 + tig]);
        qf[ks][1] = __float_as_uint(Qp[r1 + ks * 8 + tig]);
        qf[ks][2] = __float_as_uint(Qp[r0 + ks * 8 + tig + 4]);
        qf[ks][3] = __float_as_uint(Qp[r1 + ks * 8 + tig + 4]);
    }

    float o[8][4];
#pragma unroll
    for (int j = 0; j < 8; j++)
#pragma unroll
        for (int e = 0; e < 4; e++) o[j][e] = 0.f;
    float m0 = -1e30f, m1 = -1e30f, l0 = 0.f, l1 = 0.f;

    int srcA = (lane & 28) | (tig >> 1);
    int srcB = srcA + 2;
    bool oddc = tig & 1;

    const int NT = SEQ / KT;   // 64
    for (int kt = 0; kt < NT; kt++) {
        int buf = kt & 1;
        cp_wait<0>();
        __syncthreads();
        if (kt + 1 < NT) {
            stage(buf ^ 1, kt + 1);   // overwrites buffer computed LAST iter; sync above guards
            cp_commit();
        }

        // S = Q K^T (scale pre-folded into Q): 32 keys -> 4 n8 blocks
        float s[4][4];
#pragma unroll
        for (int j = 0; j < 4; j++) {
            s[j][0] = 0.f; s[j][1] = 0.f; s[j][2] = 0.f; s[j][3] = 0.f;
#pragma unroll
            for (int ks = 0; ks < 8; ks++) {
                unsigned b0 = __float_as_uint(Ks[buf][j * 8 + g][ks * 8 + tig]);
                unsigned b1 = __float_as_uint(Ks[buf][j * 8 + g][ks * 8 + tig + 4]);
                mma_tf32(s[j], qf[ks], b0, b1);
            }
        }

        // online softmax: rows g (s0,s1) and g+8 (s2,s3)
        float tm0 = -1e30f, tm1 = -1e30f;
#pragma unroll
        for (int j = 0; j < 4; j++) {
            tm0 = fmaxf(tm0, fmaxf(s[j][0], s[j][1]));
            tm1 = fmaxf(tm1, fmaxf(s[j][2], s[j][3]));
        }
        tm0 = fmaxf(tm0, __shfl_xor_sync(0xffffffffu, tm0, 1));
        tm0 = fmaxf(tm0, __shfl_xor_sync(0xffffffffu, tm0, 2));
        tm1 = fmaxf(tm1, __shfl_xor_sync(0xffffffffu, tm1, 1));
        tm1 = fmaxf(tm1, __shfl_xor_sync(0xffffffffu, tm1, 2));

        float nm0 = fmaxf(m0, tm0), nm1 = fmaxf(m1, tm1);
        float cr0 = __expf(m0 - nm0), cr1 = __expf(m1 - nm1);
        l0 *= cr0; l1 *= cr1;
#pragma unroll
        for (int j = 0; j < 8; j++) {
            o[j][0] *= cr0; o[j][1] *= cr0; o[j][2] *= cr1; o[j][3] *= cr1;
        }

        float ls0 = 0.f, ls1 = 0.f;
#pragma unroll
        for (int j = 0; j < 4; j++) {
            float p0 = __expf(s[j][0] - nm0);
            float p1 = __expf(s[j][1] - nm0);
            float p2 = __expf(s[j][2] - nm1);
            float p3 = __expf(s[j][3] - nm1);
            ls0 += p0 + p1; ls1 += p2 + p3;
            s[j][0] = p0; s[j][1] = p1; s[j][2] = p2; s[j][3] = p3;
        }
        ls0 += __shfl_xor_sync(0xffffffffu, ls0, 1);
        ls0 += __shfl_xor_sync(0xffffffffu, ls0, 2);
        ls1 += __shfl_xor_sync(0xffffffffu, ls1, 1);
        ls1 += __shfl_xor_sync(0xffffffffu, ls1, 2);
        l0 += ls0; l1 += ls1; m0 = nm0; m1 = nm1;

        // O += P V : relayout P C-frag -> A-frag via shfl, then mma
#pragma unroll
        for (int ks2 = 0; ks2 < 4; ks2++) {
            float v00 = __shfl_sync(0xffffffffu, s[ks2][0], srcA);
            float v10 = __shfl_sync(0xffffffffu, s[ks2][1], srcA);
            float v20 = __shfl_sync(0xffffffffu, s[ks2][2], srcA);
            float v30 = __shfl_sync(0xffffffffu, s[ks2][3], srcA);
            float v01 = __shfl_sync(0xffffffffu, s[ks2][0], srcB);
            float v11 = __shfl_sync(0xffffffffu, s[ks2][1], srcB);
            float v21 = __shfl_sync(0xffffffffu, s[ks2][2], srcB);
            float v31 = __shfl_sync(0xffffffffu, s[ks2][3], srcB);
            unsigned a[4];
            a[0] = __float_as_uint(oddc ? v10 : v00);
            a[1] = __float_as_uint(oddc ? v30 : v20);
            a[2] = __float_as_uint(oddc ? v11 : v01);
            a[3] = __float_as_uint(oddc ? v31 : v21);
#pragma unroll
            for (int j = 0; j < 8; j++) {
                unsigned b0 = __float_as_uint(Vs[buf][ks2 * 8 + tig][j * 8 + g]);
                unsigned b1 = __float_as_uint(Vs[buf][ks2 * 8 + tig + 4][j * 8 + g]);
                mma_tf32(o[j], a, b0, b1);
            }
        }
    }

    float i0 = 1.f / l0, i1 = 1.f / l1;
    int r0 = qrow0 + rb + g;
#pragma unroll
    for (int j = 0; j < 8; j++) {
        int c = h * DH + j * 8 + 2 * tig;
        *(float2*)(g_ctx + r0 * DIM + c)       = make_float2(o[j][0] * i0, o[j][1] * i0);
        *(float2*)(g_ctx + (r0 + 8) * DIM + c) = make_float2(o[j][2] * i1, o[j][3] * i1);
    }
}

// ---------------------------------------------------------------------------
extern "C" void kernel_launch(void* const* d_in, const int* in_sizes, int n_in,
                              void* d_out, int out_size) {
    const float* x     = (const float*)d_in[0];
    const float* Wq    = (const float*)d_in[1];
    const float* Wk    = (const float*)d_in[2];
    const float* Wv    = (const float*)d_in[3];
    const float* Wo    = (const float*)d_in[4];
    const float* gamma = (const float*)d_in[5];
    const float* beta  = (const float*)d_in[6];
    float* out = (float*)d_out;

    ln_kernel<<<ROWS, 128>>>(x, gamma, beta);
    gemm_qkv_kernel<<<dim3(DIM / BN, ROWS / BM, 3), 256>>>(x, Wq, Wk, Wv);
    flash_kernel<<<dim3(SEQ / 64, NH, BATCH), 128>>>();
    gemm_out_kernel<<<dim3(DIM / BN, ROWS / BM), 256>>>(Wo, x, out);
}

// round 13
// speedup vs baseline: 4.1132x; 1.0088x over previous
#include <cuda_runtime.h>
#include <math.h>

#define BATCH 2
#define SEQ   2048
#define DIM   512
#define NH    8
#define DH    64
#define ROWS  (BATCH*SEQ)   // 4096
#define NSPLIT 2

// Scratch (allocation-free rule: __device__ globals)
__device__ float g_xn  [ROWS*DIM];     // layernormed x (Q path)
__device__ float g_q   [ROWS*DIM];     // pre-scaled by 0.125 (1/sqrt(dh))
__device__ float g_k   [ROWS*DIM];
__device__ float g_v   [ROWS*DIM];
__device__ float g_ctx [ROWS*DIM];
__device__ float g_part[NSPLIT*ROWS*DIM];   // unnormalized partial O per split
__device__ float g_pm  [NSPLIT][ROWS*NH];   // running max per split
__device__ float g_pl  [NSPLIT][ROWS*NH];   // running denom per split

// ---------------------------------------------------------------------------
// helpers
// ---------------------------------------------------------------------------
__device__ __forceinline__ void mma_tf32(float c[4], const unsigned a[4],
                                         unsigned b0, unsigned b1) {
    asm volatile(
        "mma.sync.aligned.m16n8k8.row.col.f32.tf32.tf32.f32 "
        "{%0,%1,%2,%3},{%4,%5,%6,%7},{%8,%9},{%0,%1,%2,%3};\n"
        : "+f"(c[0]), "+f"(c[1]), "+f"(c[2]), "+f"(c[3])
        : "r"(a[0]), "r"(a[1]), "r"(a[2]), "r"(a[3]), "r"(b0), "r"(b1));
}
__device__ __forceinline__ void cpa16(unsigned dst, const void* src) {
    asm volatile("cp.async.cg.shared.global [%0], [%1], 16;\n" :: "r"(dst), "l"(src));
}
__device__ __forceinline__ void cp_commit() {
    asm volatile("cp.async.commit_group;\n");
}
template<int N>
__device__ __forceinline__ void cp_wait() {
    asm volatile("cp.async.wait_group %0;\n" :: "n"(N));
}

// ---------------------------------------------------------------------------
// LayerNorm: one block per row, 128 threads, one float4 per thread
// ---------------------------------------------------------------------------
__global__ void __launch_bounds__(128) ln_kernel(const float* __restrict__ x,
                                                 const float* __restrict__ gamma,
                                                 const float* __restrict__ beta) {
    int row = blockIdx.x;
    int tid = threadIdx.x;

    float4 v = *(const float4*)(x + row * DIM + tid * 4);
    float sum = (v.x + v.y) + (v.z + v.w);

    __shared__ float red[4];
    __shared__ float red2[4];
#pragma unroll
    for (int off = 16; off > 0; off >>= 1) sum += __shfl_xor_sync(0xffffffffu, sum, off);
    if ((tid & 31) == 0) red[tid >> 5] = sum;
    __syncthreads();
    float mean = (red[0] + red[1] + red[2] + red[3]) * (1.0f / DIM);

    float cx = v.x - mean, cy = v.y - mean, cz = v.z - mean, cw = v.w - mean;
    float sq = (cx * cx + cy * cy) + (cz * cz + cw * cw);
#pragma unroll
    for (int off = 16; off > 0; off >>= 1) sq += __shfl_xor_sync(0xffffffffu, sq, off);
    if ((tid & 31) == 0) red2[tid >> 5] = sq;
    __syncthreads();
    float var = (red2[0] + red2[1] + red2[2] + red2[3]) * (1.0f / DIM);
    float rstd = rsqrtf(var + 1e-9f);

    float4 gm = *(const float4*)(gamma + tid * 4);
    float4 bt = *(const float4*)(beta + tid * 4);
    float4 o = make_float4(gm.x * (cx * rstd) + bt.x,
                           gm.y * (cy * rstd) + bt.y,
                           gm.z * (cz * rstd) + bt.z,
                           gm.w * (cw * rstd) + bt.w);
    *(float4*)(g_xn + row * DIM + tid * 4) = o;
}

// ---------------------------------------------------------------------------
// Tensor-core tf32 GEMM, 3-stage cp.async pipeline, ONE sync per K-chunk.
// Templated CTA tile: TBM x 64, warp grid WR x WC (8 warps, 256 threads).
// ---------------------------------------------------------------------------
#define BN 64
#define BK 16
#define NSTG 3

template<int TBM, int WR, int WC>
__device__ __forceinline__ void gemm_tc_body(const float* __restrict__ A,
                                             const float* __restrict__ Wm,
                                             float* __restrict__ C,
                                             const float* __restrict__ R,
                                             float oscale) {
    constexpr int MI = TBM / (WR * 16);   // m16 blocks per warp
    constexpr int NJ = BN / (WC * 8);     // n8 blocks per warp

    __shared__ float As[NSTG][TBM][20];   // [m][k] bank ≡ (20m+k)%32 → frag-conflict-free
    __shared__ float Bs[NSTG][BK][72];    // [k][n] bank ≡ (8k+n)%32  → frag-conflict-free

    int tid = threadIdx.x;
    int w = tid >> 5, lane = tid & 31;
    int g = lane >> 2, tig = lane & 3;
    int wr = w / WC, wc = w % WC;
    int row0 = blockIdx.y * TBM;
    int col0 = blockIdx.x * BN;

    unsigned sA = (unsigned)__cvta_generic_to_shared(&As[0][0][0]);
    unsigned sB = (unsigned)__cvta_generic_to_shared(&Bs[0][0][0]);

    int br = tid >> 4, bc = (tid & 15) * 4;   // B: 256 float4 chunks, 1/thread

    float acc[MI][NJ][4];
#pragma unroll
    for (int i = 0; i < MI; i++)
#pragma unroll
        for (int j = 0; j < NJ; j++)
#pragma unroll
            for (int e = 0; e < 4; e++) acc[i][j][e] = 0.f;

    auto stage = [&](int buf, int k0) {
#pragma unroll
        for (int c = tid; c < TBM * 4; c += 256) {
            int ar = c >> 2, ac = (c & 3) * 4;
            cpa16(sA + (unsigned)(buf * (TBM * 20 * 4) + (ar * 20 + ac) * 4),
                  A + (row0 + ar) * DIM + k0 + ac);
        }
        cpa16(sB + (unsigned)(buf * (BK * 72 * 4) + (br * 72 + bc) * 4),
              Wm + (k0 + br) * DIM + col0 + bc);
    };

    stage(0, 0);        cp_commit();
    stage(1, BK);       cp_commit();

    const int NIT = DIM / BK;   // 32
    int buf = 0, nbuf = 2;
    for (int it = 0; it < NIT; it++) {
        if (it + 1 < NIT) cp_wait<1>(); else cp_wait<0>();
        __syncthreads();
        if (it + 2 < NIT) {
            stage(nbuf, (it + 2) * BK);
            cp_commit();
        }

#pragma unroll
        for (int ks = 0; ks < 2; ks++) {
            unsigned a[MI][4];
#pragma unroll
            for (int i = 0; i < MI; i++) {
                int rb = wr * (MI * 16) + i * 16;
                a[i][0] = __float_as_uint(As[buf][rb + g][ks * 8 + tig]);
                a[i][1] = __float_as_uint(As[buf][rb + g + 8][ks * 8 + tig]);
                a[i][2] = __float_as_uint(As[buf][rb + g][ks * 8 + tig + 4]);
                a[i][3] = __float_as_uint(As[buf][rb + g + 8][ks * 8 + tig + 4]);
            }
#pragma unroll
            for (int j = 0; j < NJ; j++) {
                unsigned b0 = __float_as_uint(Bs[buf][ks * 8 + tig][wc * (NJ * 8) + j * 8 + g]);
                unsigned b1 = __float_as_uint(Bs[buf][ks * 8 + tig + 4][wc * (NJ * 8) + j * 8 + g]);
#pragma unroll
                for (int i = 0; i < MI; i++) mma_tf32(acc[i][j], a[i], b0, b1);
            }
        }
        buf = (buf == NSTG - 1) ? 0 : buf + 1;
        nbuf = (nbuf == NSTG - 1) ? 0 : nbuf + 1;
    }

    // epilogue: c0=(g,2t) c1=(g,2t+1) c2=(g+8,2t) c3=(g+8,2t+1)
#pragma unroll
    for (int i = 0; i < MI; i++) {
        int r = row0 + wr * (MI * 16) + i * 16 + g;
#pragma unroll
        for (int j = 0; j < NJ; j++) {
            int c = col0 + wc * (NJ * 8) + j * 8 + 2 * tig;
            float v0 = acc[i][j][0] * oscale;
            float v1 = acc[i][j][1] * oscale;
            float v2 = acc[i][j][2] * oscale;
            float v3 = acc[i][j][3] * oscale;
            if (R) {
                v0 += R[r * DIM + c];       v1 += R[r * DIM + c + 1];
                v2 += R[(r + 8) * DIM + c]; v3 += R[(r + 8) * DIM + c + 1];
            }
            *(float2*)(C + r * DIM + c)       = make_float2(v0, v1);
            *(float2*)(C + (r + 8) * DIM + c) = make_float2(v2, v3);
        }
    }
}

__global__ void __launch_bounds__(256) gemm_qkv_kernel(const float* __restrict__ x,
                                                       const float* __restrict__ Wq,
                                                       const float* __restrict__ Wk,
                                                       const float* __restrict__ Wv) {
    const float* A; const float* Wm; float* C; float sc;
    if (blockIdx.z == 0)      { A = g_xn; Wm = Wq; C = g_q; sc = 0.125f; } // fold 1/sqrt(dh)
    else if (blockIdx.z == 1) { A = x;    Wm = Wk; C = g_k; sc = 1.0f; }
    else                      { A = x;    Wm = Wv; C = g_v; sc = 1.0f; }
    gemm_tc_body<128, 4, 2>(A, Wm, C, nullptr, sc);   // grid 768 -> well fed
}

__global__ void __launch_bounds__(256) gemm_out_kernel(const float* __restrict__ Wo,
                                                       const float* __restrict__ x,
                                                       float* __restrict__ out) {
    gemm_tc_body<64, 2, 4>(g_ctx, Wo, out, x, 1.0f);  // grid 512 -> 2x warps/SM
}

// ---------------------------------------------------------------------------
// Flash attention, split-K over key range (NSPLIT partitions), tf32 MMA.
// grid (32, 8, BATCH*NSPLIT), block 128 = 4 warps; warp w owns 16 query rows.
// Writes unnormalized partial O + (m,l); combine kernel merges splits.
// ---------------------------------------------------------------------------
#define KT 32

__global__ void __launch_bounds__(128) flash_kernel() {
    int qb = blockIdx.x, h = blockIdx.y;
    int b  = blockIdx.z >> 1, sp = blockIdx.z & 1;
    int tid = threadIdx.x;
    int w = tid >> 5, lane = tid & 31;
    int g = lane >> 2, tig = lane & 3;

    __shared__ float Ks[2][KT][68];   // bank ≡ (4row+col)%32
    __shared__ float Vs[2][KT][72];   // bank ≡ (8row+col)%32

    unsigned sK = (unsigned)__cvta_generic_to_shared(&Ks[0][0][0]);
    unsigned sV = (unsigned)__cvta_generic_to_shared(&Vs[0][0][0]);

    int qrow0 = b * SEQ + qb * 64;
    int rb = w * 16;
    const int NTH = (SEQ / KT) / NSPLIT;          // 32 tiles per split
    int kt0 = sp * NTH;
    const float* Kb = g_k + (size_t)(b * SEQ) * DIM + h * DH;
    const float* Vb = g_v + (size_t)(b * SEQ) * DIM + h * DH;

    auto stage = [&](int buf, int kt) {
#pragma unroll
        for (int t = 0; t < 4; t++) {
            int chunk = tid + t * 128;
            int row = chunk >> 4, c4 = (chunk & 15) * 4;
            const float* kp = Kb + (size_t)(kt * KT + row) * DIM + c4;
            const float* vp = Vb + (size_t)(kt * KT + row) * DIM + c4;
            cpa16(sK + (unsigned)(buf * (KT * 68 * 4) + (row * 68 + c4) * 4), kp);
            cpa16(sV + (unsigned)(buf * (KT * 72 * 4) + (row * 72 + c4) * 4), vp);
        }
    };

    stage(0, kt0);
    cp_commit();

    // Q fragments straight from gmem (once)
    unsigned qf[8][4];
    const float* Qp = g_q + h * DH;
#pragma unroll
    for (int ks = 0; ks < 8; ks++) {
        int r0 = (qrow0 + rb + g) * DIM;
        int r1 = (qrow0 + rb + g + 8) * DIM;
        qf[ks][0] = __float_as_uint(Qp[r0 + ks * 8 + tig]);
        qf[ks][1] = __float_as_uint(Qp[r1 + ks * 8 + tig]);
        qf[ks][2] = __float_as_uint(Qp[r0 + ks * 8 + tig + 4]);
        qf[ks][3] = __float_as_uint(Qp[r1 + ks * 8 + tig + 4]);
    }

    float o[8][4];
#pragma unroll
    for (int j = 0; j < 8; j++)
#pragma unroll
        for (int e = 0; e < 4; e++) o[j][e] = 0.f;
    float m0 = -1e30f, m1 = -1e30f, l0 = 0.f, l1 = 0.f;

    int srcA = (lane & 28) | (tig >> 1);
    int srcB = srcA + 2;
    bool oddc = tig & 1;

    for (int it = 0; it < NTH; it++) {
        int buf = it & 1;
        cp_wait<0>();
        __syncthreads();
        if (it + 1 < NTH) {
            stage(buf ^ 1, kt0 + it + 1);
            cp_commit();
        }

        // S = Q K^T (scale pre-folded into Q): 32 keys -> 4 n8 blocks
        float s[4][4];
#pragma unroll
        for (int j = 0; j < 4; j++) {
            s[j][0] = 0.f; s[j][1] = 0.f; s[j][2] = 0.f; s[j][3] = 0.f;
#pragma unroll
            for (int ks = 0; ks < 8; ks++) {
                unsigned b0 = __float_as_uint(Ks[buf][j * 8 + g][ks * 8 + tig]);
                unsigned b1 = __float_as_uint(Ks[buf][j * 8 + g][ks * 8 + tig + 4]);
                mma_tf32(s[j], qf[ks], b0, b1);
            }
        }

        // online softmax: rows g (s0,s1) and g+8 (s2,s3)
        float tm0 = -1e30f, tm1 = -1e30f;
#pragma unroll
        for (int j = 0; j < 4; j++) {
            tm0 = fmaxf(tm0, fmaxf(s[j][0], s[j][1]));
            tm1 = fmaxf(tm1, fmaxf(s[j][2], s[j][3]));
        }
        tm0 = fmaxf(tm0, __shfl_xor_sync(0xffffffffu, tm0, 1));
        tm0 = fmaxf(tm0, __shfl_xor_sync(0xffffffffu, tm0, 2));
        tm1 = fmaxf(tm1, __shfl_xor_sync(0xffffffffu, tm1, 1));
        tm1 = fmaxf(tm1, __shfl_xor_sync(0xffffffffu, tm1, 2));

        float nm0 = fmaxf(m0, tm0), nm1 = fmaxf(m1, tm1);
        float cr0 = __expf(m0 - nm0), cr1 = __expf(m1 - nm1);
        l0 *= cr0; l1 *= cr1;
#pragma unroll
        for (int j = 0; j < 8; j++) {
            o[j][0] *= cr0; o[j][1] *= cr0; o[j][2] *= cr1; o[j][3] *= cr1;
        }

        float ls0 = 0.f, ls1 = 0.f;
#pragma unroll
        for (int j = 0; j < 4; j++) {
            float p0 = __expf(s[j][0] - nm0);
            float p1 = __expf(s[j][1] - nm0);
            float p2 = __expf(s[j][2] - nm1);
            float p3 = __expf(s[j][3] - nm1);
            ls0 += p0 + p1; ls1 += p2 + p3;
            s[j][0] = p0; s[j][1] = p1; s[j][2] = p2; s[j][3] = p3;
        }
        ls0 += __shfl_xor_sync(0xffffffffu, ls0, 1);
        ls0 += __shfl_xor_sync(0xffffffffu, ls0, 2);
        ls1 += __shfl_xor_sync(0xffffffffu, ls1, 1);
        ls1 += __shfl_xor_sync(0xffffffffu, ls1, 2);
        l0 += ls0; l1 += ls1; m0 = nm0; m1 = nm1;

        // O += P V : relayout P C-frag -> A-frag via shfl, then mma
#pragma unroll
        for (int ks2 = 0; ks2 < 4; ks2++) {
            float v00 = __shfl_sync(0xffffffffu, s[ks2][0], srcA);
            float v10 = __shfl_sync(0xffffffffu, s[ks2][1], srcA);
            float v20 = __shfl_sync(0xffffffffu, s[ks2][2], srcA);
            float v30 = __shfl_sync(0xffffffffu, s[ks2][3], srcA);
            float v01 = __shfl_sync(0xffffffffu, s[ks2][0], srcB);
            float v11 = __shfl_sync(0xffffffffu, s[ks2][1], srcB);
            float v21 = __shfl_sync(0xffffffffu, s[ks2][2], srcB);
            float v31 = __shfl_sync(0xffffffffu, s[ks2][3], srcB);
            unsigned a[4];
            a[0] = __float_as_uint(oddc ? v10 : v00);
            a[1] = __float_as_uint(oddc ? v30 : v20);
            a[2] = __float_as_uint(oddc ? v11 : v01);
            a[3] = __float_as_uint(oddc ? v31 : v21);
#pragma unroll
            for (int j = 0; j < 8; j++) {
                unsigned b0 = __float_as_uint(Vs[buf][ks2 * 8 + tig][j * 8 + g]);
                unsigned b1 = __float_as_uint(Vs[buf][ks2 * 8 + tig + 4][j * 8 + g]);
                mma_tf32(o[j], a, b0, b1);
            }
        }
    }

    // write unnormalized partial O and (m, l)
    int r0 = qrow0 + rb + g;
    float* po = g_part + (size_t)sp * ROWS * DIM;
#pragma unroll
    for (int j = 0; j < 8; j++) {
        int c = h * DH + j * 8 + 2 * tig;
        *(float2*)(po + (size_t)r0 * DIM + c)       = make_float2(o[j][0], o[j][1]);
        *(float2*)(po + (size_t)(r0 + 8) * DIM + c) = make_float2(o[j][2], o[j][3]);
    }
    if (tig == 0) {
        g_pm[sp][r0 * NH + h] = m0;        g_pl[sp][r0 * NH + h] = l0;
        g_pm[sp][(r0 + 8) * NH + h] = m1;  g_pl[sp][(r0 + 8) * NH + h] = l1;
    }
}

// ---------------------------------------------------------------------------
// Combine splits: out = (o0*e^(m0-m) + o1*e^(m1-m)) / (l0*e^(m0-m) + l1*e^(m1-m))
// grid ROWS, 128 threads: thread t -> head t/16, float4 d-slice (t%16)*4
// ---------------------------------------------------------------------------
__global__ void __launch_bounds__(128) combine_kernel() {
    int row = blockIdx.x;
    int tid = threadIdx.x;
    int h = tid >> 4, d4 = (tid & 15) * 4;
    int rh = row * NH + h;

    float m0 = g_pm[0][rh], m1 = g_pm[1][rh];
    float l0 = g_pl[0][rh], l1 = g_pl[1][rh];
    float m = fmaxf(m0, m1);
    float w0 = __expf(m0 - m), w1 = __expf(m1 - m);
    float inv = 1.f / (l0 * w0 + l1 * w1);
    w0 *= inv; w1 *= inv;

    size_t off = (size_t)row * DIM + h * DH + d4;
    float4 o0 = *(const float4*)(g_part + off);
    float4 o1 = *(const float4*)(g_part + (size_t)ROWS * DIM + off);
    float4 r = make_float4(o0.x * w0 + o1.x * w1, o0.y * w0 + o1.y * w1,
                           o0.z * w0 + o1.z * w1, o0.w * w0 + o1.w * w1);
    *(float4*)(g_ctx + off) = r;
}

// ---------------------------------------------------------------------------
extern "C" void kernel_launch(void* const* d_in, const int* in_sizes, int n_in,
                              void* d_out, int out_size) {
    const float* x     = (const float*)d_in[0];
    const float* Wq    = (const float*)d_in[1];
    const float* Wk    = (const float*)d_in[2];
    const float* Wv    = (const float*)d_in[3];
    const float* Wo    = (const float*)d_in[4];
    const float* gamma = (const float*)d_in[5];
    const float* beta  = (const float*)d_in[6];
    float* out = (float*)d_out;

    ln_kernel<<<ROWS, 128>>>(x, gamma, beta);
    gemm_qkv_kernel<<<dim3(DIM / BN, ROWS / 128, 3), 256>>>(x, Wq, Wk, Wv);
    flash_kernel<<<dim3(SEQ / 64, NH, BATCH * NSPLIT), 128>>>();
    combine_kernel<<<ROWS, 128>>>();
    gemm_out_kernel<<<dim3(DIM / BN, ROWS / 64), 256>>>(Wo, x, out);
}

// round 14
// speedup vs baseline: 4.5487x; 1.1059x over previous
#include <cuda_runtime.h>
#include <math.h>

#define BATCH 2
#define SEQ   2048
#define DIM   512
#define NH    8
#define DH    64
#define ROWS  (BATCH*SEQ)   // 4096
#define NSPLIT 2
#define LOG2E 1.4426950408889634f

// Scratch (allocation-free rule: __device__ globals)
__device__ float g_xn  [ROWS*DIM];     // layernormed x (Q path)
__device__ float g_q   [ROWS*DIM];     // pre-scaled by 0.125*log2(e)
__device__ float g_k   [ROWS*DIM];
__device__ float g_v   [ROWS*DIM];
__device__ float g_ctx [ROWS*DIM];
__device__ float g_part[NSPLIT*ROWS*DIM];   // unnormalized partial O per split
__device__ float g_pm  [NSPLIT][ROWS*NH];   // running max per split (log2 units)
__device__ float g_pl  [NSPLIT][ROWS*NH];   // running denom per split

// ---------------------------------------------------------------------------
// helpers
// ---------------------------------------------------------------------------
__device__ __forceinline__ void mma_tf32(float c[4], const unsigned a[4],
                                         unsigned b0, unsigned b1) {
    asm volatile(
        "mma.sync.aligned.m16n8k8.row.col.f32.tf32.tf32.f32 "
        "{%0,%1,%2,%3},{%4,%5,%6,%7},{%8,%9},{%0,%1,%2,%3};\n"
        : "+f"(c[0]), "+f"(c[1]), "+f"(c[2]), "+f"(c[3])
        : "r"(a[0]), "r"(a[1]), "r"(a[2]), "r"(a[3]), "r"(b0), "r"(b1));
}
__device__ __forceinline__ void cpa16(unsigned dst, const void* src) {
    asm volatile("cp.async.cg.shared.global [%0], [%1], 16;\n" :: "r"(dst), "l"(src));
}
__device__ __forceinline__ void cp_commit() {
    asm volatile("cp.async.commit_group;\n");
}
template<int N>
__device__ __forceinline__ void cp_wait() {
    asm volatile("cp.async.wait_group %0;\n" :: "n"(N));
}

// ---------------------------------------------------------------------------
// LayerNorm: one block per row, 128 threads, one float4 per thread
// ---------------------------------------------------------------------------
__global__ void __launch_bounds__(128) ln_kernel(const float* __restrict__ x,
                                                 const float* __restrict__ gamma,
                                                 const float* __restrict__ beta) {
    int row = blockIdx.x;
    int tid = threadIdx.x;

    float4 v = *(const float4*)(x + row * DIM + tid * 4);
    float sum = (v.x + v.y) + (v.z + v.w);

    __shared__ float red[4];
    __shared__ float red2[4];
#pragma unroll
    for (int off = 16; off > 0; off >>= 1) sum += __shfl_xor_sync(0xffffffffu, sum, off);
    if ((tid & 31) == 0) red[tid >> 5] = sum;
    __syncthreads();
    float mean = (red[0] + red[1] + red[2] + red[3]) * (1.0f / DIM);

    float cx = v.x - mean, cy = v.y - mean, cz = v.z - mean, cw = v.w - mean;
    float sq = (cx * cx + cy * cy) + (cz * cz + cw * cw);
#pragma unroll
    for (int off = 16; off > 0; off >>= 1) sq += __shfl_xor_sync(0xffffffffu, sq, off);
    if ((tid & 31) == 0) red2[tid >> 5] = sq;
    __syncthreads();
    float var = (red2[0] + red2[1] + red2[2] + red2[3]) * (1.0f / DIM);
    float rstd = rsqrtf(var + 1e-9f);

    float4 gm = *(const float4*)(gamma + tid * 4);
    float4 bt = *(const float4*)(beta + tid * 4);
    float4 o = make_float4(gm.x * (cx * rstd) + bt.x,
                           gm.y * (cy * rstd) + bt.y,
                           gm.z * (cz * rstd) + bt.z,
                           gm.w * (cw * rstd) + bt.w);
    *(float4*)(g_xn + row * DIM + tid * 4) = o;
}

// ---------------------------------------------------------------------------
// Tensor-core tf32 GEMM: BM=64, BN=64, BK=32, 2-stage, one sync per K-chunk.
// 128 threads = 4 warps (2x2), warp tile 32x32 -> 32 MMAs/warp per barrier.
// ---------------------------------------------------------------------------
#define BM 64
#define BN 64
#define BK 32

__device__ __forceinline__ void gemm_tc_body(const float* __restrict__ A,
                                             const float* __restrict__ Wm,
                                             float* __restrict__ C,
                                             const float* __restrict__ R,
                                             float oscale) {
    constexpr int MI = 2;   // m16 blocks per warp
    constexpr int NJ = 4;   // n8 blocks per warp

    __shared__ float As[2][BM][36];   // [m][k] read bank ≡ (4m+k)%32 → frag-conflict-free
    __shared__ float Bs[2][BK][72];   // [k][n] read bank ≡ (8k+n)%32 → frag-conflict-free

    int tid = threadIdx.x;
    int w = tid >> 5, lane = tid & 31;
    int g = lane >> 2, tig = lane & 3;
    int wr = w >> 1, wc = w & 1;          // 2x2 warp grid, warp tile 32x32
    int row0 = blockIdx.y * BM;
    int col0 = blockIdx.x * BN;

    unsigned sA = (unsigned)__cvta_generic_to_shared(&As[0][0][0]);
    unsigned sB = (unsigned)__cvta_generic_to_shared(&Bs[0][0][0]);

    float acc[MI][NJ][4];
#pragma unroll
    for (int i = 0; i < MI; i++)
#pragma unroll
        for (int j = 0; j < NJ; j++)
#pragma unroll
            for (int e = 0; e < 4; e++) acc[i][j][e] = 0.f;

    // A: 64 rows x 8 float4-chunks = 512 chunks, 4/thread.
    // B: 32 rows x 16 chunks = 512 chunks, 4/thread.
    auto stage = [&](int buf, int k0) {
#pragma unroll
        for (int t = 0; t < 4; t++) {
            int c = tid + t * 128;
            int ar = c >> 3, ac = (c & 7) * 4;
            cpa16(sA + (unsigned)(buf * (BM * 36 * 4) + (ar * 36 + ac) * 4),
                  A + (row0 + ar) * DIM + k0 + ac);
            int br = c >> 4, bc = (c & 15) * 4;
            cpa16(sB + (unsigned)(buf * (BK * 72 * 4) + (br * 72 + bc) * 4),
                  Wm + (k0 + br) * DIM + col0 + bc);
        }
    };

    stage(0, 0);
    cp_commit();

    const int NIT = DIM / BK;   // 16
    for (int it = 0; it < NIT; it++) {
        int buf = it & 1;
        cp_wait<0>();
        __syncthreads();
        if (it + 1 < NIT) {
            stage(buf ^ 1, (it + 1) * BK);
            cp_commit();
        }

#pragma unroll
        for (int ks = 0; ks < 4; ks++) {
            unsigned a[MI][4];
#pragma unroll
            for (int i = 0; i < MI; i++) {
                int rb = wr * 32 + i * 16;
                a[i][0] = __float_as_uint(As[buf][rb + g][ks * 8 + tig]);
                a[i][1] = __float_as_uint(As[buf][rb + g + 8][ks * 8 + tig]);
                a[i][2] = __float_as_uint(As[buf][rb + g][ks * 8 + tig + 4]);
                a[i][3] = __float_as_uint(As[buf][rb + g + 8][ks * 8 + tig + 4]);
            }
#pragma unroll
            for (int j = 0; j < NJ; j++) {
                unsigned b0 = __float_as_uint(Bs[buf][ks * 8 + tig][wc * 32 + j * 8 + g]);
                unsigned b1 = __float_as_uint(Bs[buf][ks * 8 + tig + 4][wc * 32 + j * 8 + g]);
#pragma unroll
                for (int i = 0; i < MI; i++) mma_tf32(acc[i][j], a[i], b0, b1);
            }
        }
    }

    // epilogue: c0=(g,2t) c1=(g,2t+1) c2=(g+8,2t) c3=(g+8,2t+1)
#pragma unroll
    for (int i = 0; i < MI; i++) {
        int r = row0 + wr * 32 + i * 16 + g;
#pragma unroll
        for (int j = 0; j < NJ; j++) {
            int c = col0 + wc * 32 + j * 8 + 2 * tig;
            float v0 = acc[i][j][0] * oscale;
            float v1 = acc[i][j][1] * oscale;
            float v2 = acc[i][j][2] * oscale;
            float v3 = acc[i][j][3] * oscale;
            if (R) {
                v0 += R[r * DIM + c];       v1 += R[r * DIM + c + 1];
                v2 += R[(r + 8) * DIM + c]; v3 += R[(r + 8) * DIM + c + 1];
            }
            *(float2*)(C + r * DIM + c)       = make_float2(v0, v1);
            *(float2*)(C + (r + 8) * DIM + c) = make_float2(v2, v3);
        }
    }
}

__global__ void __launch_bounds__(128) gemm_qkv_kernel(const float* __restrict__ x,
                                                       const float* __restrict__ Wq,
                                                       const float* __restrict__ Wk,
                                                       const float* __restrict__ Wv) {
    const float* A; const float* Wm; float* C; float sc;
    if (blockIdx.z == 0)      { A = g_xn; Wm = Wq; C = g_q; sc = 0.125f * LOG2E; } // fold scale*log2e
    else if (blockIdx.z == 1) { A = x;    Wm = Wk; C = g_k; sc = 1.0f; }
    else                      { A = x;    Wm = Wv; C = g_v; sc = 1.0f; }
    gemm_tc_body(A, Wm, C, nullptr, sc);
}

__global__ void __launch_bounds__(128) gemm_out_kernel(const float* __restrict__ Wo,
                                                       const float* __restrict__ x,
                                                       float* __restrict__ out) {
    gemm_tc_body(g_ctx, Wo, out, x, 1.0f);
}

// ---------------------------------------------------------------------------
// Flash attention, split-K over key range (NSPLIT partitions), tf32 MMA.
// Softmax in exp2 domain (log2e folded into Q scale).
// grid (32, 8, BATCH*NSPLIT), block 128 = 4 warps; warp w owns 16 query rows.
// ---------------------------------------------------------------------------
#define KT 32

__global__ void __launch_bounds__(128) flash_kernel() {
    int qb = blockIdx.x, h = blockIdx.y;
    int b  = blockIdx.z >> 1, sp = blockIdx.z & 1;
    int tid = threadIdx.x;
    int w = tid >> 5, lane = tid & 31;
    int g = lane >> 2, tig = lane & 3;

    __shared__ float Ks[2][KT][68];   // bank ≡ (4row+col)%32
    __shared__ float Vs[2][KT][72];   // bank ≡ (8row+col)%32

    unsigned sK = (unsigned)__cvta_generic_to_shared(&Ks[0][0][0]);
    unsigned sV = (unsigned)__cvta_generic_to_shared(&Vs[0][0][0]);

    int qrow0 = b * SEQ + qb * 64;
    int rb = w * 16;
    const int NTH = (SEQ / KT) / NSPLIT;          // 32 tiles per split
    int kt0 = sp * NTH;
    const float* Kb = g_k + (size_t)(b * SEQ) * DIM + h * DH;
    const float* Vb = g_v + (size_t)(b * SEQ) * DIM + h * DH;

    auto stage = [&](int buf, int kt) {
#pragma unroll
        for (int t = 0; t < 4; t++) {
            int chunk = tid + t * 128;
            int row = chunk >> 4, c4 = (chunk & 15) * 4;
            const float* kp = Kb + (size_t)(kt * KT + row) * DIM + c4;
            const float* vp = Vb + (size_t)(kt * KT + row) * DIM + c4;
            cpa16(sK + (unsigned)(buf * (KT * 68 * 4) + (row * 68 + c4) * 4), kp);
            cpa16(sV + (unsigned)(buf * (KT * 72 * 4) + (row * 72 + c4) * 4), vp);
        }
    };

    stage(0, kt0);
    cp_commit();

    // Q fragments straight from gmem (once)
    unsigned qf[8][4];
    const float* Qp = g_q + h * DH;
#pragma unroll
    for (int ks = 0; ks < 8; ks++) {
        int r0 = (qrow0 + rb + g) * DIM;
        int r1 = (qrow0 + rb + g + 8) * DIM;
        qf[ks][0] = __float_as_uint(Qp[r0 + ks * 8 + tig]);
        qf[ks][1] = __float_as_uint(Qp[r1 + ks * 8 + tig]);
        qf[ks][2] = __float_as_uint(Qp[r0 + ks * 8 + tig + 4]);
        qf[ks][3] = __float_as_uint(Qp[r1 + ks * 8 + tig + 4]);
    }

    float o[8][4];
#pragma unroll
    for (int j = 0; j < 8; j++)
#pragma unroll
        for (int e = 0; e < 4; e++) o[j][e] = 0.f;
    float m0 = -1e30f, m1 = -1e30f, l0 = 0.f, l1 = 0.f;

    int srcA = (lane & 28) | (tig >> 1);
    int srcB = srcA + 2;
    bool oddc = tig & 1;

    for (int it = 0; it < NTH; it++) {
        int buf = it & 1;
        cp_wait<0>();
        __syncthreads();
        if (it + 1 < NTH) {
            stage(buf ^ 1, kt0 + it + 1);
            cp_commit();
        }

        // S = Q K^T (scale*log2e pre-folded into Q): 32 keys -> 4 n8 blocks
        float s[4][4];
#pragma unroll
        for (int j = 0; j < 4; j++) {
            s[j][0] = 0.f; s[j][1] = 0.f; s[j][2] = 0.f; s[j][3] = 0.f;
#pragma unroll
            for (int ks = 0; ks < 8; ks++) {
                unsigned b0 = __float_as_uint(Ks[buf][j * 8 + g][ks * 8 + tig]);
                unsigned b1 = __float_as_uint(Ks[buf][j * 8 + g][ks * 8 + tig + 4]);
                mma_tf32(s[j], qf[ks], b0, b1);
            }
        }

        // online softmax (base-2): rows g (s0,s1) and g+8 (s2,s3)
        float tm0 = -1e30f, tm1 = -1e30f;
#pragma unroll
        for (int j = 0; j < 4; j++) {
            tm0 = fmaxf(tm0, fmaxf(s[j][0], s[j][1]));
            tm1 = fmaxf(tm1, fmaxf(s[j][2], s[j][3]));
        }
        tm0 = fmaxf(tm0, __shfl_xor_sync(0xffffffffu, tm0, 1));
        tm0 = fmaxf(tm0, __shfl_xor_sync(0xffffffffu, tm0, 2));
        tm1 = fmaxf(tm1, __shfl_xor_sync(0xffffffffu, tm1, 1));
        tm1 = fmaxf(tm1, __shfl_xor_sync(0xffffffffu, tm1, 2));

        float nm0 = fmaxf(m0, tm0), nm1 = fmaxf(m1, tm1);
        float cr0 = exp2f(m0 - nm0), cr1 = exp2f(m1 - nm1);
        l0 *= cr0; l1 *= cr1;
#pragma unroll
        for (int j = 0; j < 8; j++) {
            o[j][0] *= cr0; o[j][1] *= cr0; o[j][2] *= cr1; o[j][3] *= cr1;
        }

        float ls0 = 0.f, ls1 = 0.f;
#pragma unroll
        for (int j = 0; j < 4; j++) {
            float p0 = exp2f(s[j][0] - nm0);
            float p1 = exp2f(s[j][1] - nm0);
            float p2 = exp2f(s[j][2] - nm1);
            float p3 = exp2f(s[j][3] - nm1);
            ls0 += p0 + p1; ls1 += p2 + p3;
            s[j][0] = p0; s[j][1] = p1; s[j][2] = p2; s[j][3] = p3;
        }
        ls0 += __shfl_xor_sync(0xffffffffu, ls0, 1);
        ls0 += __shfl_xor_sync(0xffffffffu, ls0, 2);
        ls1 += __shfl_xor_sync(0xffffffffu, ls1, 1);
        ls1 += __shfl_xor_sync(0xffffffffu, ls1, 2);
        l0 += ls0; l1 += ls1; m0 = nm0; m1 = nm1;

        // O += P V : relayout P C-frag -> A-frag via shfl, then mma
#pragma unroll
        for (int ks2 = 0; ks2 < 4; ks2++) {
            float v00 = __shfl_sync(0xffffffffu, s[ks2][0], srcA);
            float v10 = __shfl_sync(0xffffffffu, s[ks2][1], srcA);
            float v20 = __shfl_sync(0xffffffffu, s[ks2][2], srcA);
            float v30 = __shfl_sync(0xffffffffu, s[ks2][3], srcA);
            float v01 = __shfl_sync(0xffffffffu, s[ks2][0], srcB);
            float v11 = __shfl_sync(0xffffffffu, s[ks2][1], srcB);
            float v21 = __shfl_sync(0xffffffffu, s[ks2][2], srcB);
            float v31 = __shfl_sync(0xffffffffu, s[ks2][3], srcB);
            unsigned a[4];
            a[0] = __float_as_uint(oddc ? v10 : v00);
            a[1] = __float_as_uint(oddc ? v30 : v20);
            a[2] = __float_as_uint(oddc ? v11 : v01);
            a[3] = __float_as_uint(oddc ? v31 : v21);
#pragma unroll
            for (int j = 0; j < 8; j++) {
                unsigned b0 = __float_as_uint(Vs[buf][ks2 * 8 + tig][j * 8 + g]);
                unsigned b1 = __float_as_uint(Vs[buf][ks2 * 8 + tig + 4][j * 8 + g]);
                mma_tf32(o[j], a, b0, b1);
            }
        }
    }

    // write unnormalized partial O and (m, l)
    int r0 = qrow0 + rb + g;
    float* po = g_part + (size_t)sp * ROWS * DIM;
#pragma unroll
    for (int j = 0; j < 8; j++) {
        int c = h * DH + j * 8 + 2 * tig;
        *(float2*)(po + (size_t)r0 * DIM + c)       = make_float2(o[j][0], o[j][1]);
        *(float2*)(po + (size_t)(r0 + 8) * DIM + c) = make_float2(o[j][2], o[j][3]);
    }
    if (tig == 0) {
        g_pm[sp][r0 * NH + h] = m0;        g_pl[sp][r0 * NH + h] = l0;
        g_pm[sp][(r0 + 8) * NH + h] = m1;  g_pl[sp][(r0 + 8) * NH + h] = l1;
    }
}

// ---------------------------------------------------------------------------
// Combine splits (base-2 weights)
// ---------------------------------------------------------------------------
__global__ void __launch_bounds__(128) combine_kernel() {
    int row = blockIdx.x;
    int tid = threadIdx.x;
    int h = tid >> 4, d4 = (tid & 15) * 4;
    int rh = row * NH + h;

    float m0 = g_pm[0][rh], m1 = g_pm[1][rh];
    float l0 = g_pl[0][rh], l1 = g_pl[1][rh];
    float m = fmaxf(m0, m1);
    float w0 = exp2f(m0 - m), w1 = exp2f(m1 - m);
    float inv = 1.f / (l0 * w0 + l1 * w1);
    w0 *= inv; w1 *= inv;

    size_t off = (size_t)row * DIM + h * DH + d4;
    float4 o0 = *(const float4*)(g_part + off);
    float4 o1 = *(const float4*)(g_part + (size_t)ROWS * DIM + off);
    float4 r = make_float4(o0.x * w0 + o1.x * w1, o0.y * w0 + o1.y * w1,
                           o0.z * w0 + o1.z * w1, o0.w * w0 + o1.w * w1);
    *(float4*)(g_ctx + off) = r;
}

// ---------------------------------------------------------------------------
extern "C" void kernel_launch(void* const* d_in, const int* in_sizes, int n_in,
                              void* d_out, int out_size) {
    const float* x     = (const float*)d_in[0];
    const float* Wq    = (const float*)d_in[1];
    const float* Wk    = (const float*)d_in[2];
    const float* Wv    = (const float*)d_in[3];
    const float* Wo    = (const float*)d_in[4];
    const float* gamma = (const float*)d_in[5];
    const float* beta  = (const float*)d_in[6];
    float* out = (float*)d_out;

    ln_kernel<<<ROWS, 128>>>(x, gamma, beta);
    gemm_qkv_kernel<<<dim3(DIM / BN, ROWS / BM, 3), 128>>>(x, Wq, Wk, Wv);
    flash_kernel<<<dim3(SEQ / 64, NH, BATCH * NSPLIT), 128>>>();
    combine_kernel<<<ROWS, 128>>>();
    gemm_out_kernel<<<dim3(DIM / BN, ROWS / BM), 128>>>(Wo, x, out);
}

// round 16
// speedup vs baseline: 4.5494x; 1.0002x over previous
#include <cuda_runtime.h>
#include <math.h>

#define BATCH 2
#define SEQ   2048
#define DIM   512
#define NH    8
#define DH    64
#define ROWS  (BATCH*SEQ)   // 4096
#define NSPLIT 2
#define LOG2E 1.4426950408889634f

// Scratch (allocation-free rule: __device__ globals)
__device__ float g_xn  [ROWS*DIM];     // layernormed x (Q path)
__device__ float g_q   [ROWS*DIM];     // pre-scaled by 0.125*log2(e)
__device__ float g_k   [ROWS*DIM];
__device__ float g_v   [ROWS*DIM];
__device__ float g_ctx [ROWS*DIM];
__device__ float g_part[NSPLIT*ROWS*DIM];   // unnormalized partial O per split
__device__ float g_pm  [NSPLIT][ROWS*NH];   // running max per split (log2 units)
__device__ float g_pl  [NSPLIT][ROWS*NH];   // running denom per split

// ---------------------------------------------------------------------------
// helpers
// ---------------------------------------------------------------------------
__device__ __forceinline__ void mma_tf32(float c[4], const unsigned a[4],
                                         unsigned b0, unsigned b1) {
    asm volatile(
        "mma.sync.aligned.m16n8k8.row.col.f32.tf32.tf32.f32 "
        "{%0,%1,%2,%3},{%4,%5,%6,%7},{%8,%9},{%0,%1,%2,%3};\n"
        : "+f"(c[0]), "+f"(c[1]), "+f"(c[2]), "+f"(c[3])
        : "r"(a[0]), "r"(a[1]), "r"(a[2]), "r"(a[3]), "r"(b0), "r"(b1));
}
__device__ __forceinline__ void cpa16(unsigned dst, const void* src) {
    asm volatile("cp.async.cg.shared.global [%0], [%1], 16;\n" :: "r"(dst), "l"(src));
}
__device__ __forceinline__ void cp_commit() {
    asm volatile("cp.async.commit_group;\n");
}
template<int N>
__device__ __forceinline__ void cp_wait() {
    asm volatile("cp.async.wait_group %0;\n" :: "n"(N));
}

// ---------------------------------------------------------------------------
// LayerNorm: one block per row, 128 threads, one float4 per thread
// ---------------------------------------------------------------------------
__global__ void __launch_bounds__(128) ln_kernel(const float* __restrict__ x,
                                                 const float* __restrict__ gamma,
                                                 const float* __restrict__ beta) {
    int row = blockIdx.x;
    int tid = threadIdx.x;

    float4 v = *(const float4*)(x + row * DIM + tid * 4);
    float sum = (v.x + v.y) + (v.z + v.w);

    __shared__ float red[4];
    __shared__ float red2[4];
#pragma unroll
    for (int off = 16; off > 0; off >>= 1) sum += __shfl_xor_sync(0xffffffffu, sum, off);
    if ((tid & 31) == 0) red[tid >> 5] = sum;
    __syncthreads();
    float mean = (red[0] + red[1] + red[2] + red[3]) * (1.0f / DIM);

    float cx = v.x - mean, cy = v.y - mean, cz = v.z - mean, cw = v.w - mean;
    float sq = (cx * cx + cy * cy) + (cz * cz + cw * cw);
#pragma unroll
    for (int off = 16; off > 0; off >>= 1) sq += __shfl_xor_sync(0xffffffffu, sq, off);
    if ((tid & 31) == 0) red2[tid >> 5] = sq;
    __syncthreads();
    float var = (red2[0] + red2[1] + red2[2] + red2[3]) * (1.0f / DIM);
    float rstd = rsqrtf(var + 1e-9f);

    float4 gm = *(const float4*)(gamma + tid * 4);
    float4 bt = *(const float4*)(beta + tid * 4);
    float4 o = make_float4(gm.x * (cx * rstd) + bt.x,
                           gm.y * (cy * rstd) + bt.y,
                           gm.z * (cz * rstd) + bt.z,
                           gm.w * (cw * rstd) + bt.w);
    *(float4*)(g_xn + row * DIM + tid * 4) = o;
}

// ---------------------------------------------------------------------------
// Tensor-core tf32 GEMM: BM=64, BN=64, BK=32, 2-stage, one sync per K-chunk.
// 128 threads = 4 warps (2x2), warp tile 32x32 -> 32 MMAs/warp per barrier.
// ---------------------------------------------------------------------------
#define BM 64
#define BN 64
#define BK 32

__device__ __forceinline__ void gemm_tc_body(const float* __restrict__ A,
                                             const float* __restrict__ Wm,
                                             float* __restrict__ C,
                                             const float* __restrict__ R,
                                             float oscale) {
    constexpr int MI = 2;   // m16 blocks per warp
    constexpr int NJ = 4;   // n8 blocks per warp

    __shared__ float As[2][BM][36];   // [m][k] read bank ≡ (4m+k)%32 → frag-conflict-free
    __shared__ float Bs[2][BK][72];   // [k][n] read bank ≡ (8k+n)%32 → frag-conflict-free

    int tid = threadIdx.x;
    int w = tid >> 5, lane = tid & 31;
    int g = lane >> 2, tig = lane & 3;
    int wr = w >> 1, wc = w & 1;          // 2x2 warp grid, warp tile 32x32
    int row0 = blockIdx.y * BM;
    int col0 = blockIdx.x * BN;

    unsigned sA = (unsigned)__cvta_generic_to_shared(&As[0][0][0]);
    unsigned sB = (unsigned)__cvta_generic_to_shared(&Bs[0][0][0]);

    float acc[MI][NJ][4];
#pragma unroll
    for (int i = 0; i < MI; i++)
#pragma unroll
        for (int j = 0; j < NJ; j++)
#pragma unroll
            for (int e = 0; e < 4; e++) acc[i][j][e] = 0.f;

    // A: 64 rows x 8 float4-chunks = 512 chunks, 4/thread.
    // B: 32 rows x 16 chunks = 512 chunks, 4/thread.
    auto stage = [&](int buf, int k0) {
#pragma unroll
        for (int t = 0; t < 4; t++) {
            int c = tid + t * 128;
            int ar = c >> 3, ac = (c & 7) * 4;
            cpa16(sA + (unsigned)(buf * (BM * 36 * 4) + (ar * 36 + ac) * 4),
                  A + (row0 + ar) * DIM + k0 + ac);
            int br = c >> 4, bc = (c & 15) * 4;
            cpa16(sB + (unsigned)(buf * (BK * 72 * 4) + (br * 72 + bc) * 4),
                  Wm + (k0 + br) * DIM + col0 + bc);
        }
    };

    stage(0, 0);
    cp_commit();

    const int NIT = DIM / BK;   // 16
    for (int it = 0; it < NIT; it++) {
        int buf = it & 1;
        cp_wait<0>();
        __syncthreads();
        if (it + 1 < NIT) {
            stage(buf ^ 1, (it + 1) * BK);
            cp_commit();
        }

#pragma unroll
        for (int ks = 0; ks < 4; ks++) {
            unsigned a[MI][4];
#pragma unroll
            for (int i = 0; i < MI; i++) {
                int rb = wr * 32 + i * 16;
                a[i][0] = __float_as_uint(As[buf][rb + g][ks * 8 + tig]);
                a[i][1] = __float_as_uint(As[buf][rb + g + 8][ks * 8 + tig]);
                a[i][2] = __float_as_uint(As[buf][rb + g][ks * 8 + tig + 4]);
                a[i][3] = __float_as_uint(As[buf][rb + g + 8][ks * 8 + tig + 4]);
            }
#pragma unroll
            for (int j = 0; j < NJ; j++) {
                unsigned b0 = __float_as_uint(Bs[buf][ks * 8 + tig][wc * 32 + j * 8 + g]);
                unsigned b1 = __float_as_uint(Bs[buf][ks * 8 + tig + 4][wc * 32 + j * 8 + g]);
#pragma unroll
                for (int i = 0; i < MI; i++) mma_tf32(acc[i][j], a[i], b0, b1);
            }
        }
    }

    // epilogue: c0=(g,2t) c1=(g,2t+1) c2=(g+8,2t) c3=(g+8,2t+1)
#pragma unroll
    for (int i = 0; i < MI; i++) {
        int r = row0 + wr * 32 + i * 16 + g;
#pragma unroll
        for (int j = 0; j < NJ; j++) {
            int c = col0 + wc * 32 + j * 8 + 2 * tig;
            float v0 = acc[i][j][0] * oscale;
            float v1 = acc[i][j][1] * oscale;
            float v2 = acc[i][j][2] * oscale;
            float v3 = acc[i][j][3] * oscale;
            if (R) {
                v0 += R[r * DIM + c];       v1 += R[r * DIM + c + 1];
                v2 += R[(r + 8) * DIM + c]; v3 += R[(r + 8) * DIM + c + 1];
            }
            *(float2*)(C + r * DIM + c)       = make_float2(v0, v1);
            *(float2*)(C + (r + 8) * DIM + c) = make_float2(v2, v3);
        }
    }
}

__global__ void __launch_bounds__(128) gemm_qkv_kernel(const float* __restrict__ x,
                                                       const float* __restrict__ Wq,
                                                       const float* __restrict__ Wk,
                                                       const float* __restrict__ Wv) {
    const float* A; const float* Wm; float* C; float sc;
    if (blockIdx.z == 0)      { A = g_xn; Wm = Wq; C = g_q; sc = 0.125f * LOG2E; } // fold scale*log2e
    else if (blockIdx.z == 1) { A = x;    Wm = Wk; C = g_k; sc = 1.0f; }
    else                      { A = x;    Wm = Wv; C = g_v; sc = 1.0f; }
    gemm_tc_body(A, Wm, C, nullptr, sc);
}

__global__ void __launch_bounds__(128) gemm_out_kernel(const float* __restrict__ Wo,
                                                       const float* __restrict__ x,
                                                       float* __restrict__ out) {
    gemm_tc_body(g_ctx, Wo, out, x, 1.0f);
}

// ---------------------------------------------------------------------------
// Flash attention, split-K (NSPLIT partitions), tf32 MMA, exp2-domain softmax.
// grid (SEQ/128, NH, BATCH*NSPLIT), block 128 = 4 warps.
// Each warp owns 32 query rows (2 m16 blocks) -> CTA covers 128 q rows.
// Halves K/V L2 traffic vs 64-row CTAs; 2x MMA work per staged tile.
// ---------------------------------------------------------------------------
#define KT 32
#define FMI 2

__global__ void __launch_bounds__(128) flash_kernel() {
    int qb = blockIdx.x, h = blockIdx.y;
    int b  = blockIdx.z >> 1, sp = blockIdx.z & 1;
    int tid = threadIdx.x;
    int w = tid >> 5, lane = tid & 31;
    int g = lane >> 2, tig = lane & 3;

    __shared__ float Ks[2][KT][68];   // bank ≡ (4row+col)%32
    __shared__ float Vs[2][KT][72];   // bank ≡ (8row+col)%32

    unsigned sK = (unsigned)__cvta_generic_to_shared(&Ks[0][0][0]);
    unsigned sV = (unsigned)__cvta_generic_to_shared(&Vs[0][0][0]);

    int qrow0 = b * SEQ + qb * 128;
    int rb = w * 32;
    const int NTH = (SEQ / KT) / NSPLIT;          // 32 tiles per split
    int kt0 = sp * NTH;
    const float* Kb = g_k + (size_t)(b * SEQ) * DIM + h * DH;
    const float* Vb = g_v + (size_t)(b * SEQ) * DIM + h * DH;

    auto stage = [&](int buf, int kt) {
#pragma unroll
        for (int t = 0; t < 4; t++) {
            int chunk = tid + t * 128;
            int row = chunk >> 4, c4 = (chunk & 15) * 4;
            const float* kp = Kb + (size_t)(kt * KT + row) * DIM + c4;
            const float* vp = Vb + (size_t)(kt * KT + row) * DIM + c4;
            cpa16(sK + (unsigned)(buf * (KT * 68 * 4) + (row * 68 + c4) * 4), kp);
            cpa16(sV + (unsigned)(buf * (KT * 72 * 4) + (row * 72 + c4) * 4), vp);
        }
    };

    stage(0, kt0);
    cp_commit();

    // Q fragments straight from gmem (once): 2 m16 blocks per warp
    unsigned qf[FMI][8][4];
    const float* Qp = g_q + h * DH;
#pragma unroll
    for (int i = 0; i < FMI; i++) {
        int r0 = (qrow0 + rb + i * 16 + g) * DIM;
        int r1 = (qrow0 + rb + i * 16 + g + 8) * DIM;
#pragma unroll
        for (int ks = 0; ks < 8; ks++) {
            qf[i][ks][0] = __float_as_uint(Qp[r0 + ks * 8 + tig]);
            qf[i][ks][1] = __float_as_uint(Qp[r1 + ks * 8 + tig]);
            qf[i][ks][2] = __float_as_uint(Qp[r0 + ks * 8 + tig + 4]);
            qf[i][ks][3] = __float_as_uint(Qp[r1 + ks * 8 + tig + 4]);
        }
    }

    float o[FMI][8][4];
#pragma unroll
    for (int i = 0; i < FMI; i++)
#pragma unroll
        for (int j = 0; j < 8; j++)
#pragma unroll
            for (int e = 0; e < 4; e++) o[i][j][e] = 0.f;
    float m0[FMI], m1[FMI], l0[FMI], l1[FMI];
#pragma unroll
    for (int i = 0; i < FMI; i++) { m0[i] = -1e30f; m1[i] = -1e30f; l0[i] = 0.f; l1[i] = 0.f; }

    int srcA = (lane & 28) | (tig >> 1);
    int srcB = srcA + 2;
    bool oddc = tig & 1;

    for (int it = 0; it < NTH; it++) {
        int buf = it & 1;
        cp_wait<0>();
        __syncthreads();
        if (it + 1 < NTH) {
            stage(buf ^ 1, kt0 + it + 1);
            cp_commit();
        }

        // S = Q K^T (scale*log2e pre-folded into Q): 32 keys -> 4 n8 blocks
        float s[FMI][4][4];
#pragma unroll
        for (int j = 0; j < 4; j++) {
#pragma unroll
            for (int i = 0; i < FMI; i++) {
                s[i][j][0] = 0.f; s[i][j][1] = 0.f; s[i][j][2] = 0.f; s[i][j][3] = 0.f;
            }
#pragma unroll
            for (int ks = 0; ks < 8; ks++) {
                unsigned b0 = __float_as_uint(Ks[buf][j * 8 + g][ks * 8 + tig]);
                unsigned b1 = __float_as_uint(Ks[buf][j * 8 + g][ks * 8 + tig + 4]);
#pragma unroll
                for (int i = 0; i < FMI; i++) mma_tf32(s[i][j], qf[i][ks], b0, b1);
            }
        }

        // online softmax (base-2) per m16 block
#pragma unroll
        for (int i = 0; i < FMI; i++) {
            float tm0 = -1e30f, tm1 = -1e30f;
#pragma unroll
            for (int j = 0; j < 4; j++) {
                tm0 = fmaxf(tm0, fmaxf(s[i][j][0], s[i][j][1]));
                tm1 = fmaxf(tm1, fmaxf(s[i][j][2], s[i][j][3]));
            }
            tm0 = fmaxf(tm0, __shfl_xor_sync(0xffffffffu, tm0, 1));
            tm0 = fmaxf(tm0, __shfl_xor_sync(0xffffffffu, tm0, 2));
            tm1 = fmaxf(tm1, __shfl_xor_sync(0xffffffffu, tm1, 1));
            tm1 = fmaxf(tm1, __shfl_xor_sync(0xffffffffu, tm1, 2));

            float nm0 = fmaxf(m0[i], tm0), nm1 = fmaxf(m1[i], tm1);
            float cr0 = exp2f(m0[i] - nm0), cr1 = exp2f(m1[i] - nm1);
            l0[i] *= cr0; l1[i] *= cr1;
#pragma unroll
            for (int j = 0; j < 8; j++) {
                o[i][j][0] *= cr0; o[i][j][1] *= cr0;
                o[i][j][2] *= cr1; o[i][j][3] *= cr1;
            }

            float ls0 = 0.f, ls1 = 0.f;
#pragma unroll
            for (int j = 0; j < 4; j++) {
                float p0 = exp2f(s[i][j][0] - nm0);
                float p1 = exp2f(s[i][j][1] - nm0);
                float p2 = exp2f(s[i][j][2] - nm1);
                float p3 = exp2f(s[i][j][3] - nm1);
                ls0 += p0 + p1; ls1 += p2 + p3;
                s[i][j][0] = p0; s[i][j][1] = p1; s[i][j][2] = p2; s[i][j][3] = p3;
            }
            ls0 += __shfl_xor_sync(0xffffffffu, ls0, 1);
            ls0 += __shfl_xor_sync(0xffffffffu, ls0, 2);
            ls1 += __shfl_xor_sync(0xffffffffu, ls1, 1);
            ls1 += __shfl_xor_sync(0xffffffffu, ls1, 2);
            l0[i] += ls0; l1[i] += ls1; m0[i] = nm0; m1[i] = nm1;
        }

        // O += P V : relayout P C-frag -> A-frag via shfl, then mma
#pragma unroll
        for (int ks2 = 0; ks2 < 4; ks2++) {
            unsigned a[FMI][4];
#pragma unroll
            for (int i = 0; i < FMI; i++) {
                float v00 = __shfl_sync(0xffffffffu, s[i][ks2][0], srcA);
                float v10 = __shfl_sync(0xffffffffu, s[i][ks2][1], srcA);
                float v20 = __shfl_sync(0xffffffffu, s[i][ks2][2], srcA);
                float v30 = __shfl_sync(0xffffffffu, s[i][ks2][3], srcA);
                float v01 = __shfl_sync(0xffffffffu, s[i][ks2][0], srcB);
                float v11 = __shfl_sync(0xffffffffu, s[i][ks2][1], srcB);
                float v21 = __shfl_sync(0xffffffffu, s[i][ks2][2], srcB);
                float v31 = __shfl_sync(0xffffffffu, s[i][ks2][3], srcB);
                a[i][0] = __float_as_uint(oddc ? v10 : v00);
                a[i][1] = __float_as_uint(oddc ? v30 : v20);
                a[i][2] = __float_as_uint(oddc ? v11 : v01);
                a[i][3] = __float_as_uint(oddc ? v31 : v21);
            }
#pragma unroll
            for (int j = 0; j < 8; j++) {
                unsigned b0 = __float_as_uint(Vs[buf][ks2 * 8 + tig][j * 8 + g]);
                unsigned b1 = __float_as_uint(Vs[buf][ks2 * 8 + tig + 4][j * 8 + g]);
#pragma unroll
                for (int i = 0; i < FMI; i++) mma_tf32(o[i][j], a[i], b0, b1);
            }
        }
    }

    // write unnormalized partial O and (m, l)
    float* po = g_part + (size_t)sp * ROWS * DIM;
#pragma unroll
    for (int i = 0; i < FMI; i++) {
        int r0 = qrow0 + rb + i * 16 + g;
#pragma unroll
        for (int j = 0; j < 8; j++) {
            int c = h * DH + j * 8 + 2 * tig;
            *(float2*)(po + (size_t)r0 * DIM + c)       = make_float2(o[i][j][0], o[i][j][1]);
            *(float2*)(po + (size_t)(r0 + 8) * DIM + c) = make_float2(o[i][j][2], o[i][j][3]);
        }
        if (tig == 0) {
            g_pm[sp][r0 * NH + h] = m0[i];        g_pl[sp][r0 * NH + h] = l0[i];
            g_pm[sp][(r0 + 8) * NH + h] = m1[i];  g_pl[sp][(r0 + 8) * NH + h] = l1[i];
        }
    }
}

// ---------------------------------------------------------------------------
// Combine splits (base-2 weights)
// ---------------------------------------------------------------------------
__global__ void __launch_bounds__(128) combine_kernel() {
    int row = blockIdx.x;
    int tid = threadIdx.x;
    int h = tid >> 4, d4 = (tid & 15) * 4;
    int rh = row * NH + h;

    float m0 = g_pm[0][rh], m1 = g_pm[1][rh];
    float l0 = g_pl[0][rh], l1 = g_pl[1][rh];
    float m = fmaxf(m0, m1);
    float w0 = exp2f(m0 - m), w1 = exp2f(m1 - m);
    float inv = 1.f / (l0 * w0 + l1 * w1);
    w0 *= inv; w1 *= inv;

    size_t off = (size_t)row * DIM + h * DH + d4;
    float4 o0 = *(const float4*)(g_part + off);
    float4 o1 = *(const float4*)(g_part + (size_t)ROWS * DIM + off);
    float4 r = make_float4(o0.x * w0 + o1.x * w1, o0.y * w0 + o1.y * w1,
                           o0.z * w0 + o1.z * w1, o0.w * w0 + o1.w * w1);
    *(float4*)(g_ctx + off) = r;
}

// ---------------------------------------------------------------------------
extern "C" void kernel_launch(void* const* d_in, const int* in_sizes, int n_in,
                              void* d_out, int out_size) {
    const float* x     = (const float*)d_in[0];
    const float* Wq    = (const float*)d_in[1];
    const float* Wk    = (const float*)d_in[2];
    const float* Wv    = (const float*)d_in[3];
    const float* Wo    = (const float*)d_in[4];
    const float* gamma = (const float*)d_in[5];
    const float* beta  = (const float*)d_in[6];
    float* out = (float*)d_out;

    ln_kernel<<<ROWS, 128>>>(x, gamma, beta);
    gemm_qkv_kernel<<<dim3(DIM / BN, ROWS / BM, 3), 128>>>(x, Wq, Wk, Wv);
    flash_kernel<<<dim3(SEQ / 128, NH, BATCH * NSPLIT), 128>>>();
    combine_kernel<<<ROWS, 128>>>();
    gemm_out_kernel<<<dim3(DIM / BN, ROWS / BM), 128>>>(Wo, x, out);
}